// round 14
// baseline (speedup 1.0000x reference)
#include <cuda_runtime.h>
#include <cuda_fp16.h>
#include <cstdint>
#include <math.h>

#define DIM     2048
#define HIDDEN  5324
#define HPAD    5376
#define BATCH   16384

// ---------------- scratch ---------------------------------------------------
__device__ float  g_h1 [BATCH * DIM];               // fp32 residual 1
__device__ __half g_h2h[BATCH * DIM];               // fp16 residual 2
__device__ __half g_hn1[BATCH * DIM];
__device__ __half g_vh [BATCH * DIM];
__device__ __half g_hn2[BATCH * DIM];
__device__ __half g_ffh[(size_t)BATCH * HPAD];
__device__ __half g_wvh [DIM * DIM];
__device__ __half g_owh [DIM * DIM];
__device__ __half g_w1h [(size_t)HIDDEN * DIM];
__device__ __half g_w2h [(size_t)HIDDEN * DIM];
__device__ __half g_w3h [(size_t)DIM * HPAD];

// ---------------- PTX helpers ----------------------------------------------
__device__ __forceinline__ uint32_t smem_u32(const void* p) {
    uint32_t a;
    asm("{ .reg .u64 t; cvta.to.shared.u64 t, %1; cvt.u32.u64 %0, t; }"
        : "=r"(a) : "l"(p));
    return a;
}
__device__ __forceinline__ void cp16(uint32_t dst, const void* src, uint32_t sz) {
    asm volatile("cp.async.cg.shared.global [%0], [%1], 16, %2;"
                 :: "r"(dst), "l"(src), "r"(sz));
}
#define CP_COMMIT()  asm volatile("cp.async.commit_group;" ::: "memory")
#define CP_WAIT1()   asm volatile("cp.async.wait_group 1;" ::: "memory")

__device__ __forceinline__ void ldm4(uint32_t* r, uint32_t addr) {
    asm volatile("ldmatrix.sync.aligned.m8n8.x4.shared.b16 {%0,%1,%2,%3}, [%4];"
                 : "=r"(r[0]), "=r"(r[1]), "=r"(r[2]), "=r"(r[3]) : "r"(addr));
}
// m16n8k16 fp16 HMMA with fp16 accumulate (rt=2/SMSP, 2x fp32-acc rate).
// C fragment: c[0] = halves {(g,2t),(g,2t+1)}, c[1] = {(g+8,2t),(g+8,2t+1)}.
__device__ __forceinline__ void mma16h(uint32_t* c, const uint32_t* a, const uint32_t* b) {
    asm volatile(
        "mma.sync.aligned.m16n8k16.row.col.f16.f16.f16.f16 "
        "{%0,%1}, {%2,%3,%4,%5}, {%6,%7}, {%0,%1};"
        : "+r"(c[0]), "+r"(c[1])
        : "r"(a[0]), "r"(a[1]), "r"(a[2]), "r"(a[3]), "r"(b[0]), "r"(b[1]));
}

// ---------------- merged weight conversion (wv, ow, w1, w2) -----------------
#define N1_F4 (DIM * DIM / 4)
#define N2_F4 (HIDDEN * DIM / 4)
__global__ void __launch_bounds__(256) f2h_all_kernel(
    const float* __restrict__ wv, const float* __restrict__ ow,
    const float* __restrict__ w1, const float* __restrict__ w2,
    __half* __restrict__ wvh, __half* __restrict__ owh,
    __half* __restrict__ w1h, __half* __restrict__ w2h)
{
    int i = blockIdx.x * 256 + threadIdx.x;
    const float* s;  __half* d;  int j;
    if      (i < N1_F4)                 { s = wv; d = wvh; j = i; }
    else if (i < 2 * N1_F4)             { s = ow; d = owh; j = i - N1_F4; }
    else if (i < 2 * N1_F4 + N2_F4)     { s = w1; d = w1h; j = i - 2 * N1_F4; }
    else if (i < 2 * N1_F4 + 2 * N2_F4) { s = w2; d = w2h; j = i - 2 * N1_F4 - N2_F4; }
    else return;
    float4 v = ((const float4*)s)[j];
    __half2* o = (__half2*)d + j * 2;
    o[0] = __floats2half2_rn(v.x, v.y);
    o[1] = __floats2half2_rn(v.z, v.w);
}
__global__ void __launch_bounds__(256) f2h_pad_kernel(const float* __restrict__ s,
                                                      __half* __restrict__ d,
                                                      int rows, int cols, int ldd)
{
    int i = blockIdx.x * 256 + threadIdx.x;
    int total = rows * ldd;
    if (i < total) {
        int r = i / ldd, c = i - r * ldd;
        d[i] = (c < cols) ? __float2half(s[(size_t)r * cols + c]) : __half(0.f);
    }
}

// ---------------- add + rmsnorm (fp32 in) -> fp32 h, fp16 hn ---------------
__global__ void __launch_bounds__(256) rmsnorm_add_kernel(
    const float* __restrict__ a, const float* __restrict__ b,
    const float* __restrict__ g,
    float* __restrict__ h_out, __half* __restrict__ hn_out)
{
    const int row = blockIdx.x;
    const size_t base = (size_t)row * DIM;
    const float4* a4 = (const float4*)(a + base);
    const float4* b4 = (const float4*)(b + base);
    const float4* g4 = (const float4*)g;

    float4 v[2];
    float ss = 0.f;
#pragma unroll
    for (int i = 0; i < 2; i++) {
        int idx = threadIdx.x + i * 256;
        float4 x = a4[idx];
        float4 y = b4[idx];
        x.x += y.x; x.y += y.y; x.z += y.z; x.w += y.w;
        v[i] = x;
        ss += x.x * x.x + x.y * x.y + x.z * x.z + x.w * x.w;
    }
    __shared__ float red[8];
#pragma unroll
    for (int o = 16; o; o >>= 1) ss += __shfl_xor_sync(0xffffffffu, ss, o);
    if ((threadIdx.x & 31) == 0) red[threadIdx.x >> 5] = ss;
    __syncthreads();
    float tot = red[0] + red[1] + red[2] + red[3] + red[4] + red[5] + red[6] + red[7];

    const float inv = 0.022097086912079613f / fmaxf(sqrtf(tot), 1e-12f);

    float4*  h4   = (float4*)(h_out + base);
    __half2* hn2p = (__half2*)(hn_out + base);
#pragma unroll
    for (int i = 0; i < 2; i++) {
        int idx = threadIdx.x + i * 256;
        float4 x = v[i];
        h4[idx] = x;
        float4 gg = g4[idx];
        hn2p[idx * 2 + 0] = __floats2half2_rn(x.x * inv * gg.x, x.y * inv * gg.y);
        hn2p[idx * 2 + 1] = __floats2half2_rn(x.z * inv * gg.z, x.w * inv * gg.w);
    }
}

// ---------------- rmsnorm (fp16 in) -> fp16 out -----------------------------
__global__ void __launch_bounds__(256) rmsnorm_h_kernel(
    const __half* __restrict__ a, const float* __restrict__ g,
    __half* __restrict__ hn)
{
    const int row = blockIdx.x;
    const size_t base = (size_t)row * DIM;
    uint4 pk = ((const uint4*)(a + base))[threadIdx.x];
    __half2* hp = (__half2*)&pk;
    float2 f[4];
    float ss = 0.f;
#pragma unroll
    for (int k = 0; k < 4; k++) {
        f[k] = __half22float2(hp[k]);
        ss += f[k].x * f[k].x + f[k].y * f[k].y;
    }
    __shared__ float red[8];
#pragma unroll
    for (int o = 16; o; o >>= 1) ss += __shfl_xor_sync(0xffffffffu, ss, o);
    if ((threadIdx.x & 31) == 0) red[threadIdx.x >> 5] = ss;
    __syncthreads();
    float tot = red[0] + red[1] + red[2] + red[3] + red[4] + red[5] + red[6] + red[7];

    const float inv = 0.022097086912079613f / fmaxf(sqrtf(tot), 1e-12f);

    const float4* g4 = (const float4*)g + threadIdx.x * 2;
    float4 g0 = g4[0], g1 = g4[1];
    uint4 out;
    __half2* op = (__half2*)&out;
    op[0] = __floats2half2_rn(f[0].x * inv * g0.x, f[0].y * inv * g0.y);
    op[1] = __floats2half2_rn(f[1].x * inv * g0.z, f[1].y * inv * g0.w);
    op[2] = __floats2half2_rn(f[2].x * inv * g1.x, f[2].y * inv * g1.y);
    op[3] = __floats2half2_rn(f[3].x * inv * g1.z, f[3].y * inv * g1.w);
    ((uint4*)(hn + base))[threadIdx.x] = out;
}

// ---------------- fp16 HMMA GEMM, fp16 accumulate (K, N compile-time) -------
// RESM: 0 none, 1 fp32 residual, 2 fp16 residual.
// CTA 128x128, 4 warps, warp 64x64, m16n8k16.f16 acc, 3-stage, in-chunk
// barrier + cross-chunk fragment prefetch.
template <bool BIAS, int RESM, bool HALF_OUT, int N, int K>
__global__ void __launch_bounds__(128, 2) gemm_h(
    const __half* __restrict__ A, const __half* __restrict__ B,
    const float* __restrict__ bias, const void* __restrict__ resv,
    void* __restrict__ Cv)
{
    extern __shared__ __half sh[];
    const int tid = threadIdx.x, wid = tid >> 5, lane = tid & 31;
    const int q = lane >> 2, t = lane & 3;
    const int m0 = blockIdx.y * 128, n0 = blockIdx.x * 128;
    const int wm = (wid >> 1) * 64, wn = (wid & 1) * 64;
    constexpr int KT = K >> 6;
    const uint32_t sbase = smem_u32(sh);

    const int lr = tid >> 3, lc = tid & 7;
    const __half* Ab = A + (size_t)(m0 + lr) * K + lc * 8;
    const __half* Bb = B + (size_t)(n0 + lr) * K + lc * 8;
    const uint32_t dA = sbase + (uint32_t)(lr * 144 + lc * 16);
    const uint32_t dB = dA + 18432u;

    auto load = [&](int kc_, int s) {
        const int k0 = kc_ << 6;
        const uint32_t so = (uint32_t)(s * 36864);
#pragma unroll
        for (int i = 0; i < 8; i++)
            cp16(dA + so + (uint32_t)(i * 16 * 144), Ab + k0 + (size_t)i * 16 * K, 16u);
#pragma unroll
        for (int i = 0; i < 8; i++)
            cp16(dB + so + (uint32_t)(i * 16 * 144), Bb + k0 + (size_t)i * 16 * K, 16u);
        CP_COMMIT();
    };

    uint32_t acc[4][8][2] = {};          // fp16x2 accumulators (zero bits = +0)
    load(0, 0);
    load(1, 1);

    const uint32_t a_lane_off = (uint32_t)((lane & 15) * 144 + ((lane >> 4) << 4));
    const uint32_t b_lane_off = (uint32_t)(((lane & 7) + ((lane >> 4) << 3)) * 144
                                           + (((lane >> 3) & 1) << 4));

    uint32_t af[2][4][4], bf[2][8][2];

    auto fetch_a = [&](uint32_t ab, int ks, int buf) {
#pragma unroll
        for (int mt = 0; mt < 4; mt++)
            ldm4(af[buf][mt], ab + (uint32_t)(mt * 16 * 144 + ks * 32));
    };
    auto fetch_b = [&](uint32_t bb, int ks, int buf) {
#pragma unroll
        for (int p = 0; p < 4; p++) {
            uint32_t r4[4];
            ldm4(r4, bb + (uint32_t)(p * 16 * 144 + ks * 32));
            bf[buf][2 * p][0] = r4[0]; bf[buf][2 * p][1] = r4[1];
            bf[buf][2 * p + 1][0] = r4[2]; bf[buf][2 * p + 1][1] = r4[3];
        }
    };

    int s = 0;
    CP_WAIT1();
    __syncthreads();
    fetch_a(sbase + (uint32_t)(wm * 144) + a_lane_off, 0, 0);
    fetch_b(sbase + 18432u + (uint32_t)(wn * 144) + b_lane_off, 0, 0);

    for (int kc = 0; kc < KT; kc++) {
        if (kc + 2 < KT) load(kc + 2, (s + 2) % 3);
        else             CP_COMMIT();

        const uint32_t as = sbase + s * 36864u;
        const uint32_t ab = as + (uint32_t)(wm * 144) + a_lane_off;
        const uint32_t bb = as + 18432u + (uint32_t)(wn * 144) + b_lane_off;

#pragma unroll
        for (int ks = 0; ks < 4; ks++) {
            const int cur = ks & 1, nxt = cur ^ 1;
            if (ks < 3) {
                fetch_a(ab, ks + 1, nxt);
                fetch_b(bb, ks + 1, nxt);
            } else if (kc + 1 < KT) {
                CP_WAIT1();
                __syncthreads();
                const int s1 = (s == 2) ? 0 : s + 1;
                const uint32_t as1 = sbase + s1 * 36864u;
                fetch_a(as1 + (uint32_t)(wm * 144) + a_lane_off, 0, nxt);
                fetch_b(as1 + 18432u + (uint32_t)(wn * 144) + b_lane_off, 0, nxt);
            }
#pragma unroll
            for (int mt = 0; mt < 4; mt++)
#pragma unroll
                for (int nt = 0; nt < 8; nt++)
                    mma16h(acc[mt][nt], af[cur][mt], bf[cur][nt]);
        }
        s = (s == 2) ? 0 : s + 1;
    }

    // epilogue: acc[..][0] = row g cols (2t,2t+1); acc[..][1] = row g+8
#pragma unroll
    for (int mt = 0; mt < 4; mt++) {
#pragma unroll
        for (int half = 0; half < 2; half++) {
            const int r = m0 + wm + mt * 16 + q + half * 8;
#pragma unroll
            for (int nt = 0; nt < 8; nt++) {
                int n = n0 + wn + nt * 8 + 2 * t;
                float2 c = __half22float2(*(__half2*)&acc[mt][nt][half]);
                float vx = c.x, vy = c.y;
                if (BIAS) { float2 b = *(const float2*)&bias[n]; vx += b.x; vy += b.y; }
                if (RESM == 1) {
                    const float2 rr = *(const float2*)((const float*)resv + (size_t)r * N + n);
                    vx += rr.x; vy += rr.y;
                } else if (RESM == 2) {
                    const __half2 rr = *(const __half2*)((const __half*)resv + (size_t)r * N + n);
                    vx += __half2float(rr.x); vy += __half2float(rr.y);
                }
                if (HALF_OUT)
                    *(__half2*)((__half*)Cv + (size_t)r * N + n) = __floats2half2_rn(vx, vy);
                else
                    *(float2*)((float*)Cv + (size_t)r * N + n) = make_float2(vx, vy);
            }
        }
    }
}

// ---------------- fp16 dual GEMM (fp16 acc): C = silu(A@B1^T)*(A@B2^T) -----
// CTA 128x64, 4 warps, warp 64x32 per matrix, K compile-time (=DIM).
template <int K>
__global__ void __launch_bounds__(128, 2) gemm_dual_h(
    const __half* __restrict__ A, const __half* __restrict__ B1,
    const __half* __restrict__ B2, __half* __restrict__ C)
{
    extern __shared__ __half sh[];
    const int tid = threadIdx.x, wid = tid >> 5, lane = tid & 31;
    const int q = lane >> 2, t = lane & 3;
    const int m0 = blockIdx.y * 128, n0 = blockIdx.x * 64;
    const int wm = (wid >> 1) * 64, wn = (wid & 1) * 32;
    constexpr int KT = K >> 6;
    const uint32_t sbase = smem_u32(sh);
    const bool interior = (n0 + 64 <= HIDDEN);

    const int lr = tid >> 3, lc = tid & 7;
    const __half* Ab  = A + (size_t)(m0 + lr) * K + lc * 8;
    const int  brow   = n0 + lr;
    const uint32_t dA  = sbase + (uint32_t)(lr * 144 + lc * 16);
    const uint32_t dB1 = dA + 18432u;
    const uint32_t dB2 = dA + 27648u;

    auto load = [&](int kc_, int s) {
        const int k0 = kc_ << 6;
        const uint32_t so = (uint32_t)(s * 36864);
#pragma unroll
        for (int i = 0; i < 8; i++)
            cp16(dA + so + (uint32_t)(i * 16 * 144), Ab + k0 + (size_t)i * 16 * K, 16u);
        if (interior) {
#pragma unroll
            for (int i = 0; i < 4; i++) {
                size_t off = (size_t)(brow + i * 16) * K + lc * 8 + k0;
                cp16(dB1 + so + (uint32_t)(i * 16 * 144), B1 + off, 16u);
                cp16(dB2 + so + (uint32_t)(i * 16 * 144), B2 + off, 16u);
            }
        } else {
#pragma unroll
            for (int i = 0; i < 4; i++) {
                uint32_t ok = (brow + i * 16 < HIDDEN) ? 16u : 0u;
                size_t off = (size_t)(ok ? (brow + i * 16) : 0) * K + lc * 8 + k0;
                cp16(dB1 + so + (uint32_t)(i * 16 * 144), B1 + off, ok);
                cp16(dB2 + so + (uint32_t)(i * 16 * 144), B2 + off, ok);
            }
        }
        CP_COMMIT();
    };

    uint32_t acc1[4][4][2] = {};
    uint32_t acc2[4][4][2] = {};
    load(0, 0);
    load(1, 1);

    const uint32_t a_lane_off = (uint32_t)((lane & 15) * 144 + ((lane >> 4) << 4));
    const uint32_t b_lane_off = (uint32_t)(((lane & 7) + ((lane >> 4) << 3)) * 144
                                           + (((lane >> 3) & 1) << 4));

    uint32_t af[2][4][4], b1f[2][4][2], b2f[2][4][2];

    auto fetch_a = [&](uint32_t ab, int ks, int buf) {
#pragma unroll
        for (int mt = 0; mt < 4; mt++)
            ldm4(af[buf][mt], ab + (uint32_t)(mt * 16 * 144 + ks * 32));
    };
    auto fetch_b = [&](uint32_t b1b, uint32_t b2b, int ks, int buf) {
#pragma unroll
        for (int p = 0; p < 2; p++) {
            uint32_t r4[4];
            ldm4(r4, b1b + (uint32_t)(p * 16 * 144 + ks * 32));
            b1f[buf][2 * p][0] = r4[0]; b1f[buf][2 * p][1] = r4[1];
            b1f[buf][2 * p + 1][0] = r4[2]; b1f[buf][2 * p + 1][1] = r4[3];
            ldm4(r4, b2b + (uint32_t)(p * 16 * 144 + ks * 32));
            b2f[buf][2 * p][0] = r4[0]; b2f[buf][2 * p][1] = r4[1];
            b2f[buf][2 * p + 1][0] = r4[2]; b2f[buf][2 * p + 1][1] = r4[3];
        }
    };

    int s = 0;
    CP_WAIT1();
    __syncthreads();
    fetch_a(sbase + (uint32_t)(wm * 144) + a_lane_off, 0, 0);
    fetch_b(sbase + 18432u + (uint32_t)(wn * 144) + b_lane_off,
            sbase + 27648u + (uint32_t)(wn * 144) + b_lane_off, 0, 0);

    for (int kc = 0; kc < KT; kc++) {
        if (kc + 2 < KT) load(kc + 2, (s + 2) % 3);
        else             CP_COMMIT();

        const uint32_t as  = sbase + s * 36864u;
        const uint32_t ab  = as + (uint32_t)(wm * 144) + a_lane_off;
        const uint32_t b1b = as + 18432u + (uint32_t)(wn * 144) + b_lane_off;
        const uint32_t b2b = as + 27648u + (uint32_t)(wn * 144) + b_lane_off;

#pragma unroll
        for (int ks = 0; ks < 4; ks++) {
            const int cur = ks & 1, nxt = cur ^ 1;
            if (ks < 3) {
                fetch_a(ab, ks + 1, nxt);
                fetch_b(b1b, b2b, ks + 1, nxt);
            } else if (kc + 1 < KT) {
                CP_WAIT1();
                __syncthreads();
                const int s1 = (s == 2) ? 0 : s + 1;
                const uint32_t as1 = sbase + s1 * 36864u;
                fetch_a(as1 + (uint32_t)(wm * 144) + a_lane_off, 0, nxt);
                fetch_b(as1 + 18432u + (uint32_t)(wn * 144) + b_lane_off,
                        as1 + 27648u + (uint32_t)(wn * 144) + b_lane_off, 0, nxt);
            }
#pragma unroll
            for (int mt = 0; mt < 4; mt++)
#pragma unroll
                for (int nt = 0; nt < 4; nt++) {
                    mma16h(acc1[mt][nt], af[cur][mt], b1f[cur][nt]);
                    mma16h(acc2[mt][nt], af[cur][mt], b2f[cur][nt]);
                }
        }
        s = (s == 2) ? 0 : s + 1;
    }

    // epilogue: silu(acc1) * acc2 -> fp16 (pads come out zero)
#pragma unroll
    for (int mt = 0; mt < 4; mt++) {
#pragma unroll
        for (int half = 0; half < 2; half++) {
            const int r = m0 + wm + mt * 16 + q + half * 8;
            __half* Crow = C + (size_t)r * HPAD;
#pragma unroll
            for (int nt = 0; nt < 4; nt++) {
                int n = n0 + wn + nt * 8 + 2 * t;
                float2 u = __half22float2(*(__half2*)&acc1[mt][nt][half]);
                float2 v = __half22float2(*(__half2*)&acc2[mt][nt][half]);
                float o0 = u.x / (1.f + expf(-u.x)) * v.x;
                float o1 = u.y / (1.f + expf(-u.y)) * v.y;
                *(__half2*)&Crow[n] = __floats2half2_rn(o0, o1);
            }
        }
    }
}

// ---------------- launch ---------------------------------------------------
extern "C" void kernel_launch(void* const* d_in, const int* in_sizes, int n_in,
                              void* d_out, int out_size)
{
    const float* x          = (const float*)d_in[0];
    const float* state      = (const float*)d_in[1];
    const float* g1         = (const float*)d_in[2];
    const float* g2         = (const float*)d_in[3];
    const float* in_proj_w  = (const float*)d_in[4];
    const float* in_proj_b  = (const float*)d_in[5];
    const float* out_proj_w = (const float*)d_in[6];
    const float* out_proj_b = (const float*)d_in[7];
    const float* w1         = (const float*)d_in[8];
    const float* w2         = (const float*)d_in[9];
    const float* w3         = (const float*)d_in[10];
    float* out = (float*)d_out;

    const float* wv = in_proj_w + (size_t)2 * DIM * DIM;
    const float* bv = in_proj_b + 2 * DIM;

    float *h1;  __half *h2h, *hn1, *vh, *hn2, *ffh, *wvh, *owh, *w1h, *w2h, *w3h;
    cudaGetSymbolAddress((void**)&h1,  g_h1);
    cudaGetSymbolAddress((void**)&h2h, g_h2h);
    cudaGetSymbolAddress((void**)&hn1, g_hn1);
    cudaGetSymbolAddress((void**)&vh,  g_vh);
    cudaGetSymbolAddress((void**)&hn2, g_hn2);
    cudaGetSymbolAddress((void**)&ffh, g_ffh);
    cudaGetSymbolAddress((void**)&wvh, g_wvh);
    cudaGetSymbolAddress((void**)&owh, g_owh);
    cudaGetSymbolAddress((void**)&w1h, g_w1h);
    cudaGetSymbolAddress((void**)&w2h, g_w2h);
    cudaGetSymbolAddress((void**)&w3h, g_w3h);

    const int SMEM = 110592;   // 3 stages x 36864 B
    cudaFuncSetAttribute((const void*)gemm_h<true,  0, true,  DIM, DIM >, cudaFuncAttributeMaxDynamicSharedMemorySize, SMEM);
    cudaFuncSetAttribute((const void*)gemm_h<true,  1, true,  DIM, DIM >, cudaFuncAttributeMaxDynamicSharedMemorySize, SMEM);
    cudaFuncSetAttribute((const void*)gemm_h<false, 2, false, DIM, HPAD>, cudaFuncAttributeMaxDynamicSharedMemorySize, SMEM);
    cudaFuncSetAttribute((const void*)gemm_dual_h<DIM>,                   cudaFuncAttributeMaxDynamicSharedMemorySize, SMEM);

    // 0. weight conversions
    {
        int tot4 = 2 * N1_F4 + 2 * N2_F4;
        f2h_all_kernel<<<(tot4 + 255) / 256, 256>>>(wv, out_proj_w, w1, w2,
                                                    wvh, owh, w1h, w2h);
        int tot = DIM * HPAD;
        f2h_pad_kernel<<<(tot + 255) / 256, 256>>>(w3, w3h, DIM, HIDDEN, HPAD);
    }

    // 1. h1 = x + state (fp32) ; hn1 = rmsnorm(h1, g1) -> fp16
    rmsnorm_add_kernel<<<BATCH, 256>>>(x, state, g1, h1, hn1);

    // 2. v = hn1 @ wv^T + bv -> fp16
    gemm_h<true, 0, true, DIM, DIM><<<dim3(DIM / 128, BATCH / 128), 128, SMEM>>>(
        hn1, wvh, bv, nullptr, vh);

    // 3. h2 = h1 + v @ out_proj_w^T + out_proj_b -> fp16
    gemm_h<true, 1, true, DIM, DIM><<<dim3(DIM / 128, BATCH / 128), 128, SMEM>>>(
        vh, owh, out_proj_b, h1, h2h);

    // 4. hn2 = rmsnorm(h2, g2) -> fp16
    rmsnorm_h_kernel<<<BATCH, 256>>>(h2h, g2, hn2);

    // 5. ffh = silu(hn2 @ w1^T) * (hn2 @ w2^T) -> fp16 (padded to HPAD)
    gemm_dual_h<DIM><<<dim3(HPAD / 64, BATCH / 128), 128, SMEM>>>(
        hn2, w1h, w2h, ffh);

    // 6. out = h2 + ffh @ w3^T -> fp32 (K = HPAD; fp16 residual)
    gemm_h<false, 2, false, DIM, HPAD><<<dim3(DIM / 128, BATCH / 128), 128, SMEM>>>(
        ffh, w3h, nullptr, h2h, out);
}

// round 15
// speedup vs baseline: 1.0785x; 1.0785x over previous
#include <cuda_runtime.h>
#include <cuda_fp16.h>
#include <cstdint>
#include <math.h>

#define DIM     2048
#define HIDDEN  5324
#define HPAD    5376
#define BATCH   16384

// ---------------- scratch ---------------------------------------------------
__device__ float  g_h1 [BATCH * DIM];               // fp32 residual 1
__device__ __half g_h2h[BATCH * DIM];               // fp16 residual 2
__device__ __half g_hn1[BATCH * DIM];
__device__ __half g_vh [BATCH * DIM];
__device__ __half g_hn2[BATCH * DIM];
__device__ __half g_ffh[(size_t)BATCH * HPAD];
__device__ __half g_wvh [DIM * DIM];
__device__ __half g_owh [DIM * DIM];
__device__ __half g_w1h [(size_t)HIDDEN * DIM];
__device__ __half g_w2h [(size_t)HIDDEN * DIM];
__device__ __half g_w3h [(size_t)DIM * HPAD];

// ---------------- PTX helpers ----------------------------------------------
__device__ __forceinline__ uint32_t smem_u32(const void* p) {
    uint32_t a;
    asm("{ .reg .u64 t; cvta.to.shared.u64 t, %1; cvt.u32.u64 %0, t; }"
        : "=r"(a) : "l"(p));
    return a;
}
__device__ __forceinline__ void cp16(uint32_t dst, const void* src, uint32_t sz) {
    asm volatile("cp.async.cg.shared.global [%0], [%1], 16, %2;"
                 :: "r"(dst), "l"(src), "r"(sz));
}
#define CP_COMMIT()  asm volatile("cp.async.commit_group;" ::: "memory")
#define CP_WAIT0()   asm volatile("cp.async.wait_group 0;" ::: "memory")
#define CP_WAIT1()   asm volatile("cp.async.wait_group 1;" ::: "memory")

__device__ __forceinline__ void ldm4(uint32_t* r, uint32_t addr) {
    asm volatile("ldmatrix.sync.aligned.m8n8.x4.shared.b16 {%0,%1,%2,%3}, [%4];"
                 : "=r"(r[0]), "=r"(r[1]), "=r"(r[2]), "=r"(r[3]) : "r"(addr));
}
// m16n8k16 fp16 HMMA, fp16 accumulate (same rate as f32-acc; fewer regs).
__device__ __forceinline__ void mma16h(uint32_t* c, const uint32_t* a, const uint32_t* b) {
    asm volatile(
        "mma.sync.aligned.m16n8k16.row.col.f16.f16.f16.f16 "
        "{%0,%1}, {%2,%3,%4,%5}, {%6,%7}, {%0,%1};"
        : "+r"(c[0]), "+r"(c[1])
        : "r"(a[0]), "r"(a[1]), "r"(a[2]), "r"(a[3]), "r"(b[0]), "r"(b[1]));
}

// ---------------- merged weight conversion (wv, ow, w1, w2) -----------------
#define N1_F4 (DIM * DIM / 4)
#define N2_F4 (HIDDEN * DIM / 4)
__global__ void __launch_bounds__(256) f2h_all_kernel(
    const float* __restrict__ wv, const float* __restrict__ ow,
    const float* __restrict__ w1, const float* __restrict__ w2,
    __half* __restrict__ wvh, __half* __restrict__ owh,
    __half* __restrict__ w1h, __half* __restrict__ w2h)
{
    int i = blockIdx.x * 256 + threadIdx.x;
    const float* s;  __half* d;  int j;
    if      (i < N1_F4)                 { s = wv; d = wvh; j = i; }
    else if (i < 2 * N1_F4)             { s = ow; d = owh; j = i - N1_F4; }
    else if (i < 2 * N1_F4 + N2_F4)     { s = w1; d = w1h; j = i - 2 * N1_F4; }
    else if (i < 2 * N1_F4 + 2 * N2_F4) { s = w2; d = w2h; j = i - 2 * N1_F4 - N2_F4; }
    else return;
    float4 v = ((const float4*)s)[j];
    __half2* o = (__half2*)d + j * 2;
    o[0] = __floats2half2_rn(v.x, v.y);
    o[1] = __floats2half2_rn(v.z, v.w);
}
__global__ void __launch_bounds__(256) f2h_pad_kernel(const float* __restrict__ s,
                                                      __half* __restrict__ d,
                                                      int rows, int cols, int ldd)
{
    int i = blockIdx.x * 256 + threadIdx.x;
    int total = rows * ldd;
    if (i < total) {
        int r = i / ldd, c = i - r * ldd;
        d[i] = (c < cols) ? __float2half(s[(size_t)r * cols + c]) : __half(0.f);
    }
}

// ---------------- add + rmsnorm (fp32 in) -> fp32 h, fp16 hn ---------------
__global__ void __launch_bounds__(256) rmsnorm_add_kernel(
    const float* __restrict__ a, const float* __restrict__ b,
    const float* __restrict__ g,
    float* __restrict__ h_out, __half* __restrict__ hn_out)
{
    const int row = blockIdx.x;
    const size_t base = (size_t)row * DIM;
    const float4* a4 = (const float4*)(a + base);
    const float4* b4 = (const float4*)(b + base);
    const float4* g4 = (const float4*)g;

    float4 v[2];
    float ss = 0.f;
#pragma unroll
    for (int i = 0; i < 2; i++) {
        int idx = threadIdx.x + i * 256;
        float4 x = a4[idx];
        float4 y = b4[idx];
        x.x += y.x; x.y += y.y; x.z += y.z; x.w += y.w;
        v[i] = x;
        ss += x.x * x.x + x.y * x.y + x.z * x.z + x.w * x.w;
    }
    __shared__ float red[8];
#pragma unroll
    for (int o = 16; o; o >>= 1) ss += __shfl_xor_sync(0xffffffffu, ss, o);
    if ((threadIdx.x & 31) == 0) red[threadIdx.x >> 5] = ss;
    __syncthreads();
    float tot = red[0] + red[1] + red[2] + red[3] + red[4] + red[5] + red[6] + red[7];

    const float inv = 0.022097086912079613f / fmaxf(sqrtf(tot), 1e-12f);

    float4*  h4   = (float4*)(h_out + base);
    __half2* hn2p = (__half2*)(hn_out + base);
#pragma unroll
    for (int i = 0; i < 2; i++) {
        int idx = threadIdx.x + i * 256;
        float4 x = v[i];
        h4[idx] = x;
        float4 gg = g4[idx];
        hn2p[idx * 2 + 0] = __floats2half2_rn(x.x * inv * gg.x, x.y * inv * gg.y);
        hn2p[idx * 2 + 1] = __floats2half2_rn(x.z * inv * gg.z, x.w * inv * gg.w);
    }
}

// ---------------- rmsnorm (fp16 in) -> fp16 out -----------------------------
__global__ void __launch_bounds__(256) rmsnorm_h_kernel(
    const __half* __restrict__ a, const float* __restrict__ g,
    __half* __restrict__ hn)
{
    const int row = blockIdx.x;
    const size_t base = (size_t)row * DIM;
    uint4 pk = ((const uint4*)(a + base))[threadIdx.x];
    __half2* hp = (__half2*)&pk;
    float2 f[4];
    float ss = 0.f;
#pragma unroll
    for (int k = 0; k < 4; k++) {
        f[k] = __half22float2(hp[k]);
        ss += f[k].x * f[k].x + f[k].y * f[k].y;
    }
    __shared__ float red[8];
#pragma unroll
    for (int o = 16; o; o >>= 1) ss += __shfl_xor_sync(0xffffffffu, ss, o);
    if ((threadIdx.x & 31) == 0) red[threadIdx.x >> 5] = ss;
    __syncthreads();
    float tot = red[0] + red[1] + red[2] + red[3] + red[4] + red[5] + red[6] + red[7];

    const float inv = 0.022097086912079613f / fmaxf(sqrtf(tot), 1e-12f);

    const float4* g4 = (const float4*)g + threadIdx.x * 2;
    float4 g0 = g4[0], g1 = g4[1];
    uint4 out;
    __half2* op = (__half2*)&out;
    op[0] = __floats2half2_rn(f[0].x * inv * g0.x, f[0].y * inv * g0.y);
    op[1] = __floats2half2_rn(f[1].x * inv * g0.z, f[1].y * inv * g0.w);
    op[2] = __floats2half2_rn(f[2].x * inv * g1.x, f[2].y * inv * g1.y);
    op[3] = __floats2half2_rn(f[3].x * inv * g1.z, f[3].y * inv * g1.w);
    ((uint4*)(hn + base))[threadIdx.x] = out;
}

// ---------------- fp16 HMMA GEMM, 2-stage, 3 CTAs/SM ------------------------
// RESM: 0 none, 1 fp32 residual, 2 fp16 residual.
// CTA 128x128, 4 warps, warp 64x64, m16n8k16.f16 acc.
// 2-stage cp.async; at ks==3: wait_group 0 (only next chunk's group is in
// flight, issued one full chunk earlier) + barrier, prefetch next-chunk
// fragments from stage s^1, then refill stage s with chunk kc+2.
template <bool BIAS, int RESM, bool HALF_OUT, int N, int K>
__global__ void __launch_bounds__(128, 3) gemm_h(
    const __half* __restrict__ A, const __half* __restrict__ B,
    const float* __restrict__ bias, const void* __restrict__ resv,
    void* __restrict__ Cv)
{
    extern __shared__ __half sh[];
    const int tid = threadIdx.x, wid = tid >> 5, lane = tid & 31;
    const int q = lane >> 2, t = lane & 3;
    const int m0 = blockIdx.y * 128, n0 = blockIdx.x * 128;
    const int wm = (wid >> 1) * 64, wn = (wid & 1) * 64;
    constexpr int KT = K >> 6;
    const uint32_t sbase = smem_u32(sh);

    const int lr = tid >> 3, lc = tid & 7;
    const __half* Ab = A + (size_t)(m0 + lr) * K + lc * 8;
    const __half* Bb = B + (size_t)(n0 + lr) * K + lc * 8;
    const uint32_t dA = sbase + (uint32_t)(lr * 144 + lc * 16);
    const uint32_t dB = dA + 18432u;

    auto load = [&](int kc_, int s) {
        const int k0 = kc_ << 6;
        const uint32_t so = (uint32_t)(s * 36864);
#pragma unroll
        for (int i = 0; i < 8; i++)
            cp16(dA + so + (uint32_t)(i * 16 * 144), Ab + k0 + (size_t)i * 16 * K, 16u);
#pragma unroll
        for (int i = 0; i < 8; i++)
            cp16(dB + so + (uint32_t)(i * 16 * 144), Bb + k0 + (size_t)i * 16 * K, 16u);
        CP_COMMIT();
    };

    uint32_t acc[4][8][2] = {};
    load(0, 0);
    load(1, 1);

    const uint32_t a_lane_off = (uint32_t)((lane & 15) * 144 + ((lane >> 4) << 4));
    const uint32_t b_lane_off = (uint32_t)(((lane & 7) + ((lane >> 4) << 3)) * 144
                                           + (((lane >> 3) & 1) << 4));

    uint32_t af[2][4][4], bf[2][8][2];

    auto fetch_a = [&](uint32_t ab, int ks, int buf) {
#pragma unroll
        for (int mt = 0; mt < 4; mt++)
            ldm4(af[buf][mt], ab + (uint32_t)(mt * 16 * 144 + ks * 32));
    };
    auto fetch_b = [&](uint32_t bb, int ks, int buf) {
#pragma unroll
        for (int p = 0; p < 4; p++) {
            uint32_t r4[4];
            ldm4(r4, bb + (uint32_t)(p * 16 * 144 + ks * 32));
            bf[buf][2 * p][0] = r4[0]; bf[buf][2 * p][1] = r4[1];
            bf[buf][2 * p + 1][0] = r4[2]; bf[buf][2 * p + 1][1] = r4[3];
        }
    };

    int s = 0;
    CP_WAIT1();                // group0 (chunk0) complete; group1 may fly
    __syncthreads();
    fetch_a(sbase + (uint32_t)(wm * 144) + a_lane_off, 0, 0);
    fetch_b(sbase + 18432u + (uint32_t)(wn * 144) + b_lane_off, 0, 0);

    for (int kc = 0; kc < KT; kc++) {
        const uint32_t as = sbase + s * 36864u;
        const uint32_t ab = as + (uint32_t)(wm * 144) + a_lane_off;
        const uint32_t bb = as + 18432u + (uint32_t)(wn * 144) + b_lane_off;

#pragma unroll
        for (int ks = 0; ks < 4; ks++) {
            const int cur = ks & 1, nxt = cur ^ 1;
            if (ks < 3) {
                fetch_a(ab, ks + 1, nxt);
                fetch_b(bb, ks + 1, nxt);
            } else if (kc + 1 < KT) {
                CP_WAIT0();            // chunk kc+1 resident (issued 1 chunk ago)
                __syncthreads();       // all warps done reading stage s
                const uint32_t as1 = sbase + (s ^ 1) * 36864u;
                fetch_a(as1 + (uint32_t)(wm * 144) + a_lane_off, 0, nxt);
                fetch_b(as1 + 18432u + (uint32_t)(wn * 144) + b_lane_off, 0, nxt);
                if (kc + 2 < KT) load(kc + 2, s);   // refill freed stage
            }
#pragma unroll
            for (int mt = 0; mt < 4; mt++)
#pragma unroll
                for (int nt = 0; nt < 8; nt++)
                    mma16h(acc[mt][nt], af[cur][mt], bf[cur][nt]);
        }
        s ^= 1;
    }

    // epilogue: acc[..][0] = row g cols (2t,2t+1); acc[..][1] = row g+8
#pragma unroll
    for (int mt = 0; mt < 4; mt++) {
#pragma unroll
        for (int half = 0; half < 2; half++) {
            const int r = m0 + wm + mt * 16 + q + half * 8;
#pragma unroll
            for (int nt = 0; nt < 8; nt++) {
                int n = n0 + wn + nt * 8 + 2 * t;
                float2 c = __half22float2(*(__half2*)&acc[mt][nt][half]);
                float vx = c.x, vy = c.y;
                if (BIAS) { float2 b = *(const float2*)&bias[n]; vx += b.x; vy += b.y; }
                if (RESM == 1) {
                    const float2 rr = *(const float2*)((const float*)resv + (size_t)r * N + n);
                    vx += rr.x; vy += rr.y;
                } else if (RESM == 2) {
                    const __half2 rr = *(const __half2*)((const __half*)resv + (size_t)r * N + n);
                    vx += __half2float(rr.x); vy += __half2float(rr.y);
                }
                if (HALF_OUT)
                    *(__half2*)((__half*)Cv + (size_t)r * N + n) = __floats2half2_rn(vx, vy);
                else
                    *(float2*)((float*)Cv + (size_t)r * N + n) = make_float2(vx, vy);
            }
        }
    }
}

// ---------------- fp16 dual GEMM (fp16 acc), 2-stage, 3 CTAs/SM ------------
// CTA 128x64, 4 warps, warp 64x32 per matrix, K compile-time (=DIM).
template <int K>
__global__ void __launch_bounds__(128, 3) gemm_dual_h(
    const __half* __restrict__ A, const __half* __restrict__ B1,
    const __half* __restrict__ B2, __half* __restrict__ C)
{
    extern __shared__ __half sh[];
    const int tid = threadIdx.x, wid = tid >> 5, lane = tid & 31;
    const int q = lane >> 2, t = lane & 3;
    const int m0 = blockIdx.y * 128, n0 = blockIdx.x * 64;
    const int wm = (wid >> 1) * 64, wn = (wid & 1) * 32;
    constexpr int KT = K >> 6;
    const uint32_t sbase = smem_u32(sh);
    const bool interior = (n0 + 64 <= HIDDEN);

    const int lr = tid >> 3, lc = tid & 7;
    const __half* Ab  = A + (size_t)(m0 + lr) * K + lc * 8;
    const int  brow   = n0 + lr;
    const uint32_t dA  = sbase + (uint32_t)(lr * 144 + lc * 16);
    const uint32_t dB1 = dA + 18432u;
    const uint32_t dB2 = dA + 27648u;

    auto load = [&](int kc_, int s) {
        const int k0 = kc_ << 6;
        const uint32_t so = (uint32_t)(s * 36864);
#pragma unroll
        for (int i = 0; i < 8; i++)
            cp16(dA + so + (uint32_t)(i * 16 * 144), Ab + k0 + (size_t)i * 16 * K, 16u);
        if (interior) {
#pragma unroll
            for (int i = 0; i < 4; i++) {
                size_t off = (size_t)(brow + i * 16) * K + lc * 8 + k0;
                cp16(dB1 + so + (uint32_t)(i * 16 * 144), B1 + off, 16u);
                cp16(dB2 + so + (uint32_t)(i * 16 * 144), B2 + off, 16u);
            }
        } else {
#pragma unroll
            for (int i = 0; i < 4; i++) {
                uint32_t ok = (brow + i * 16 < HIDDEN) ? 16u : 0u;
                size_t off = (size_t)(ok ? (brow + i * 16) : 0) * K + lc * 8 + k0;
                cp16(dB1 + so + (uint32_t)(i * 16 * 144), B1 + off, ok);
                cp16(dB2 + so + (uint32_t)(i * 16 * 144), B2 + off, ok);
            }
        }
        CP_COMMIT();
    };

    uint32_t acc1[4][4][2] = {};
    uint32_t acc2[4][4][2] = {};
    load(0, 0);
    load(1, 1);

    const uint32_t a_lane_off = (uint32_t)((lane & 15) * 144 + ((lane >> 4) << 4));
    const uint32_t b_lane_off = (uint32_t)(((lane & 7) + ((lane >> 4) << 3)) * 144
                                           + (((lane >> 3) & 1) << 4));

    uint32_t af[2][4][4], b1f[2][4][2], b2f[2][4][2];

    auto fetch_a = [&](uint32_t ab, int ks, int buf) {
#pragma unroll
        for (int mt = 0; mt < 4; mt++)
            ldm4(af[buf][mt], ab + (uint32_t)(mt * 16 * 144 + ks * 32));
    };
    auto fetch_b = [&](uint32_t b1b, uint32_t b2b, int ks, int buf) {
#pragma unroll
        for (int p = 0; p < 2; p++) {
            uint32_t r4[4];
            ldm4(r4, b1b + (uint32_t)(p * 16 * 144 + ks * 32));
            b1f[buf][2 * p][0] = r4[0]; b1f[buf][2 * p][1] = r4[1];
            b1f[buf][2 * p + 1][0] = r4[2]; b1f[buf][2 * p + 1][1] = r4[3];
            ldm4(r4, b2b + (uint32_t)(p * 16 * 144 + ks * 32));
            b2f[buf][2 * p][0] = r4[0]; b2f[buf][2 * p][1] = r4[1];
            b2f[buf][2 * p + 1][0] = r4[2]; b2f[buf][2 * p + 1][1] = r4[3];
        }
    };

    int s = 0;
    CP_WAIT1();
    __syncthreads();
    fetch_a(sbase + (uint32_t)(wm * 144) + a_lane_off, 0, 0);
    fetch_b(sbase + 18432u + (uint32_t)(wn * 144) + b_lane_off,
            sbase + 27648u + (uint32_t)(wn * 144) + b_lane_off, 0, 0);

    for (int kc = 0; kc < KT; kc++) {
        const uint32_t as  = sbase + s * 36864u;
        const uint32_t ab  = as + (uint32_t)(wm * 144) + a_lane_off;
        const uint32_t b1b = as + 18432u + (uint32_t)(wn * 144) + b_lane_off;
        const uint32_t b2b = as + 27648u + (uint32_t)(wn * 144) + b_lane_off;

#pragma unroll
        for (int ks = 0; ks < 4; ks++) {
            const int cur = ks & 1, nxt = cur ^ 1;
            if (ks < 3) {
                fetch_a(ab, ks + 1, nxt);
                fetch_b(b1b, b2b, ks + 1, nxt);
            } else if (kc + 1 < KT) {
                CP_WAIT0();
                __syncthreads();
                const uint32_t as1 = sbase + (s ^ 1) * 36864u;
                fetch_a(as1 + (uint32_t)(wm * 144) + a_lane_off, 0, nxt);
                fetch_b(as1 + 18432u + (uint32_t)(wn * 144) + b_lane_off,
                        as1 + 27648u + (uint32_t)(wn * 144) + b_lane_off, 0, nxt);
                if (kc + 2 < KT) load(kc + 2, s);
            }
#pragma unroll
            for (int mt = 0; mt < 4; mt++)
#pragma unroll
                for (int nt = 0; nt < 4; nt++) {
                    mma16h(acc1[mt][nt], af[cur][mt], b1f[cur][nt]);
                    mma16h(acc2[mt][nt], af[cur][mt], b2f[cur][nt]);
                }
        }
        s ^= 1;
    }

    // epilogue: silu(acc1) * acc2 -> fp16 (pads come out zero)
#pragma unroll
    for (int mt = 0; mt < 4; mt++) {
#pragma unroll
        for (int half = 0; half < 2; half++) {
            const int r = m0 + wm + mt * 16 + q + half * 8;
            __half* Crow = C + (size_t)r * HPAD;
#pragma unroll
            for (int nt = 0; nt < 4; nt++) {
                int n = n0 + wn + nt * 8 + 2 * t;
                float2 u = __half22float2(*(__half2*)&acc1[mt][nt][half]);
                float2 v = __half22float2(*(__half2*)&acc2[mt][nt][half]);
                float o0 = u.x / (1.f + expf(-u.x)) * v.x;
                float o1 = u.y / (1.f + expf(-u.y)) * v.y;
                *(__half2*)&Crow[n] = __floats2half2_rn(o0, o1);
            }
        }
    }
}

// ---------------- launch ---------------------------------------------------
extern "C" void kernel_launch(void* const* d_in, const int* in_sizes, int n_in,
                              void* d_out, int out_size)
{
    const float* x          = (const float*)d_in[0];
    const float* state      = (const float*)d_in[1];
    const float* g1         = (const float*)d_in[2];
    const float* g2         = (const float*)d_in[3];
    const float* in_proj_w  = (const float*)d_in[4];
    const float* in_proj_b  = (const float*)d_in[5];
    const float* out_proj_w = (const float*)d_in[6];
    const float* out_proj_b = (const float*)d_in[7];
    const float* w1         = (const float*)d_in[8];
    const float* w2         = (const float*)d_in[9];
    const float* w3         = (const float*)d_in[10];
    float* out = (float*)d_out;

    const float* wv = in_proj_w + (size_t)2 * DIM * DIM;
    const float* bv = in_proj_b + 2 * DIM;

    float *h1;  __half *h2h, *hn1, *vh, *hn2, *ffh, *wvh, *owh, *w1h, *w2h, *w3h;
    cudaGetSymbolAddress((void**)&h1,  g_h1);
    cudaGetSymbolAddress((void**)&h2h, g_h2h);
    cudaGetSymbolAddress((void**)&hn1, g_hn1);
    cudaGetSymbolAddress((void**)&vh,  g_vh);
    cudaGetSymbolAddress((void**)&hn2, g_hn2);
    cudaGetSymbolAddress((void**)&ffh, g_ffh);
    cudaGetSymbolAddress((void**)&wvh, g_wvh);
    cudaGetSymbolAddress((void**)&owh, g_owh);
    cudaGetSymbolAddress((void**)&w1h, g_w1h);
    cudaGetSymbolAddress((void**)&w2h, g_w2h);
    cudaGetSymbolAddress((void**)&w3h, g_w3h);

    const int SMEM = 73728;   // 2 stages x 36864 B -> 3 CTAs/SM
    cudaFuncSetAttribute((const void*)gemm_h<true,  0, true,  DIM, DIM >, cudaFuncAttributeMaxDynamicSharedMemorySize, SMEM);
    cudaFuncSetAttribute((const void*)gemm_h<true,  1, true,  DIM, DIM >, cudaFuncAttributeMaxDynamicSharedMemorySize, SMEM);
    cudaFuncSetAttribute((const void*)gemm_h<false, 2, false, DIM, HPAD>, cudaFuncAttributeMaxDynamicSharedMemorySize, SMEM);
    cudaFuncSetAttribute((const void*)gemm_dual_h<DIM>,                   cudaFuncAttributeMaxDynamicSharedMemorySize, SMEM);

    // 0. weight conversions
    {
        int tot4 = 2 * N1_F4 + 2 * N2_F4;
        f2h_all_kernel<<<(tot4 + 255) / 256, 256>>>(wv, out_proj_w, w1, w2,
                                                    wvh, owh, w1h, w2h);
        int tot = DIM * HPAD;
        f2h_pad_kernel<<<(tot + 255) / 256, 256>>>(w3, w3h, DIM, HIDDEN, HPAD);
    }

    // 1. h1 = x + state (fp32) ; hn1 = rmsnorm(h1, g1) -> fp16
    rmsnorm_add_kernel<<<BATCH, 256>>>(x, state, g1, h1, hn1);

    // 2. v = hn1 @ wv^T + bv -> fp16
    gemm_h<true, 0, true, DIM, DIM><<<dim3(DIM / 128, BATCH / 128), 128, SMEM>>>(
        hn1, wvh, bv, nullptr, vh);

    // 3. h2 = h1 + v @ out_proj_w^T + out_proj_b -> fp16
    gemm_h<true, 1, true, DIM, DIM><<<dim3(DIM / 128, BATCH / 128), 128, SMEM>>>(
        vh, owh, out_proj_b, h1, h2h);

    // 4. hn2 = rmsnorm(h2, g2) -> fp16
    rmsnorm_h_kernel<<<BATCH, 256>>>(h2h, g2, hn2);

    // 5. ffh = silu(hn2 @ w1^T) * (hn2 @ w2^T) -> fp16 (padded to HPAD)
    gemm_dual_h<DIM><<<dim3(HPAD / 64, BATCH / 128), 128, SMEM>>>(
        hn2, w1h, w2h, ffh);

    // 6. out = h2 + ffh @ w3^T -> fp32 (K = HPAD; fp16 residual)
    gemm_h<false, 2, false, DIM, HPAD><<<dim3(DIM / 128, BATCH / 128), 128, SMEM>>>(
        ffh, w3h, nullptr, h2h, out);
}

// round 16
// speedup vs baseline: 1.0924x; 1.0129x over previous
#include <cuda_runtime.h>
#include <cuda_fp16.h>
#include <cstdint>
#include <math.h>

#define DIM     2048
#define HIDDEN  5324
#define HPAD    5376
#define BATCH   16384

// ---------------- scratch ---------------------------------------------------
__device__ __half g_h1h[BATCH * DIM];               // fp16 residual 1
__device__ __half g_h2h[BATCH * DIM];               // fp16 residual 2
__device__ __half g_hn1[BATCH * DIM];
__device__ __half g_vh [BATCH * DIM];
__device__ __half g_hn2[BATCH * DIM];
__device__ __half g_ffh[(size_t)BATCH * HPAD];
__device__ __half g_wvh [DIM * DIM];
__device__ __half g_owh [DIM * DIM];
__device__ __half g_w1h [(size_t)HIDDEN * DIM];
__device__ __half g_w2h [(size_t)HIDDEN * DIM];
__device__ __half g_w3h [(size_t)DIM * HPAD];

// ---------------- PTX helpers ----------------------------------------------
__device__ __forceinline__ uint32_t smem_u32(const void* p) {
    uint32_t a;
    asm("{ .reg .u64 t; cvta.to.shared.u64 t, %1; cvt.u32.u64 %0, t; }"
        : "=r"(a) : "l"(p));
    return a;
}
__device__ __forceinline__ void cp16(uint32_t dst, const void* src, uint32_t sz) {
    asm volatile("cp.async.cg.shared.global [%0], [%1], 16, %2;"
                 :: "r"(dst), "l"(src), "r"(sz));
}
#define CP_COMMIT()  asm volatile("cp.async.commit_group;" ::: "memory")
#define CP_WAIT0()   asm volatile("cp.async.wait_group 0;" ::: "memory")
#define CP_WAIT1()   asm volatile("cp.async.wait_group 1;" ::: "memory")

__device__ __forceinline__ void ldm4(uint32_t* r, uint32_t addr) {
    asm volatile("ldmatrix.sync.aligned.m8n8.x4.shared.b16 {%0,%1,%2,%3}, [%4];"
                 : "=r"(r[0]), "=r"(r[1]), "=r"(r[2]), "=r"(r[3]) : "r"(addr));
}
// m16n8k16 fp16 HMMA, fp16 accumulate
__device__ __forceinline__ void mma16h(uint32_t* c, const uint32_t* a, const uint32_t* b) {
    asm volatile(
        "mma.sync.aligned.m16n8k16.row.col.f16.f16.f16.f16 "
        "{%0,%1}, {%2,%3,%4,%5}, {%6,%7}, {%0,%1};"
        : "+r"(c[0]), "+r"(c[1])
        : "r"(a[0]), "r"(a[1]), "r"(a[2]), "r"(a[3]), "r"(b[0]), "r"(b[1]));
}

// ---------------- merged weight conversion (wv, ow, w1, w2, w3pad) ----------
#define N1_F4 (DIM * DIM / 4)
#define N2_F4 (HIDDEN * DIM / 4)
#define N3_F4 (DIM * HPAD / 4)          // w3 padded dest, float4-equivalent units
#define TOT_F4 (2 * N1_F4 + 2 * N2_F4 + N3_F4)
__global__ void __launch_bounds__(256) f2h_all_kernel(
    const float* __restrict__ wv, const float* __restrict__ ow,
    const float* __restrict__ w1, const float* __restrict__ w2,
    const float* __restrict__ w3,
    __half* __restrict__ wvh, __half* __restrict__ owh,
    __half* __restrict__ w1h, __half* __restrict__ w2h,
    __half* __restrict__ w3h)
{
    int i = blockIdx.x * 256 + threadIdx.x;
    if (i >= TOT_F4) return;
    if (i < 2 * N1_F4 + 2 * N2_F4) {
        const float* s;  __half* d;  int j;
        if      (i < N1_F4)             { s = wv; d = wvh; j = i; }
        else if (i < 2 * N1_F4)         { s = ow; d = owh; j = i - N1_F4; }
        else if (i < 2 * N1_F4 + N2_F4) { s = w1; d = w1h; j = i - 2 * N1_F4; }
        else                            { s = w2; d = w2h; j = i - 2 * N1_F4 - N2_F4; }
        float4 v = ((const float4*)s)[j];
        __half2* o = (__half2*)d + j * 2;
        o[0] = __floats2half2_rn(v.x, v.y);
        o[1] = __floats2half2_rn(v.z, v.w);
    } else {
        // w3 pad: dest is [DIM, HPAD] fp16, src [DIM, HIDDEN] fp32; group of 4
        int j = i - (2 * N1_F4 + 2 * N2_F4);           // 0 .. N3_F4-1
        int r = j / (HPAD / 4), cg = j - r * (HPAD / 4);
        int c = cg * 4;
        float4 v = make_float4(0.f, 0.f, 0.f, 0.f);
        if (c < HIDDEN)                                 // HIDDEN % 4 == 0
            v = *(const float4*)&w3[(size_t)r * HIDDEN + c];
        __half2* o = (__half2*)(w3h + (size_t)r * HPAD + c);
        o[0] = __floats2half2_rn(v.x, v.y);
        o[1] = __floats2half2_rn(v.z, v.w);
    }
}

// ---------------- add + rmsnorm (fp32 in) -> fp16 h, fp16 hn ----------------
__global__ void __launch_bounds__(256) rmsnorm_add_kernel(
    const float* __restrict__ a, const float* __restrict__ b,
    const float* __restrict__ g,
    __half* __restrict__ h_out, __half* __restrict__ hn_out)
{
    const int row = blockIdx.x;
    const size_t base = (size_t)row * DIM;
    const float4* a4 = (const float4*)(a + base);
    const float4* b4 = (const float4*)(b + base);
    const float4* g4 = (const float4*)g;

    float4 v[2];
    float ss = 0.f;
#pragma unroll
    for (int i = 0; i < 2; i++) {
        int idx = threadIdx.x + i * 256;
        float4 x = a4[idx];
        float4 y = b4[idx];
        x.x += y.x; x.y += y.y; x.z += y.z; x.w += y.w;
        v[i] = x;
        ss += x.x * x.x + x.y * x.y + x.z * x.z + x.w * x.w;
    }
    __shared__ float red[8];
#pragma unroll
    for (int o = 16; o; o >>= 1) ss += __shfl_xor_sync(0xffffffffu, ss, o);
    if ((threadIdx.x & 31) == 0) red[threadIdx.x >> 5] = ss;
    __syncthreads();
    float tot = red[0] + red[1] + red[2] + red[3] + red[4] + red[5] + red[6] + red[7];

    const float inv = 0.022097086912079613f / fmaxf(sqrtf(tot), 1e-12f);

    __half2* h2p  = (__half2*)(h_out + base);
    __half2* hn2p = (__half2*)(hn_out + base);
#pragma unroll
    for (int i = 0; i < 2; i++) {
        int idx = threadIdx.x + i * 256;
        float4 x = v[i];
        h2p[idx * 2 + 0] = __floats2half2_rn(x.x, x.y);
        h2p[idx * 2 + 1] = __floats2half2_rn(x.z, x.w);
        float4 gg = g4[idx];
        hn2p[idx * 2 + 0] = __floats2half2_rn(x.x * inv * gg.x, x.y * inv * gg.y);
        hn2p[idx * 2 + 1] = __floats2half2_rn(x.z * inv * gg.z, x.w * inv * gg.w);
    }
}

// ---------------- rmsnorm (fp16 in) -> fp16 out -----------------------------
__global__ void __launch_bounds__(256) rmsnorm_h_kernel(
    const __half* __restrict__ a, const float* __restrict__ g,
    __half* __restrict__ hn)
{
    const int row = blockIdx.x;
    const size_t base = (size_t)row * DIM;
    uint4 pk = ((const uint4*)(a + base))[threadIdx.x];
    __half2* hp = (__half2*)&pk;
    float2 f[4];
    float ss = 0.f;
#pragma unroll
    for (int k = 0; k < 4; k++) {
        f[k] = __half22float2(hp[k]);
        ss += f[k].x * f[k].x + f[k].y * f[k].y;
    }
    __shared__ float red[8];
#pragma unroll
    for (int o = 16; o; o >>= 1) ss += __shfl_xor_sync(0xffffffffu, ss, o);
    if ((threadIdx.x & 31) == 0) red[threadIdx.x >> 5] = ss;
    __syncthreads();
    float tot = red[0] + red[1] + red[2] + red[3] + red[4] + red[5] + red[6] + red[7];

    const float inv = 0.022097086912079613f / fmaxf(sqrtf(tot), 1e-12f);

    const float4* g4 = (const float4*)g + threadIdx.x * 2;
    float4 g0 = g4[0], g1 = g4[1];
    uint4 out;
    __half2* op = (__half2*)&out;
    op[0] = __floats2half2_rn(f[0].x * inv * g0.x, f[0].y * inv * g0.y);
    op[1] = __floats2half2_rn(f[1].x * inv * g0.z, f[1].y * inv * g0.w);
    op[2] = __floats2half2_rn(f[2].x * inv * g1.x, f[2].y * inv * g1.y);
    op[3] = __floats2half2_rn(f[3].x * inv * g1.z, f[3].y * inv * g1.w);
    ((uint4*)(hn + base))[threadIdx.x] = out;
}

// ---------------- fp16 HMMA GEMM, 2-stage, 3 CTAs/SM (R15 pipeline) ---------
// RESM: 0 none, 2 fp16 residual.
template <bool BIAS, int RESM, bool HALF_OUT, int N, int K>
__global__ void __launch_bounds__(128, 3) gemm_h(
    const __half* __restrict__ A, const __half* __restrict__ B,
    const float* __restrict__ bias, const void* __restrict__ resv,
    void* __restrict__ Cv)
{
    extern __shared__ __half sh[];
    const int tid = threadIdx.x, wid = tid >> 5, lane = tid & 31;
    const int q = lane >> 2, t = lane & 3;
    const int m0 = blockIdx.y * 128, n0 = blockIdx.x * 128;
    const int wm = (wid >> 1) * 64, wn = (wid & 1) * 64;
    constexpr int KT = K >> 6;
    const uint32_t sbase = smem_u32(sh);

    const int lr = tid >> 3, lc = tid & 7;
    const __half* Ab = A + (size_t)(m0 + lr) * K + lc * 8;
    const __half* Bb = B + (size_t)(n0 + lr) * K + lc * 8;
    const uint32_t dA = sbase + (uint32_t)(lr * 144 + lc * 16);
    const uint32_t dB = dA + 18432u;

    auto load = [&](int kc_, int s) {
        const int k0 = kc_ << 6;
        const uint32_t so = (uint32_t)(s * 36864);
#pragma unroll
        for (int i = 0; i < 8; i++)
            cp16(dA + so + (uint32_t)(i * 16 * 144), Ab + k0 + (size_t)i * 16 * K, 16u);
#pragma unroll
        for (int i = 0; i < 8; i++)
            cp16(dB + so + (uint32_t)(i * 16 * 144), Bb + k0 + (size_t)i * 16 * K, 16u);
        CP_COMMIT();
    };

    uint32_t acc[4][8][2] = {};
    load(0, 0);
    load(1, 1);

    const uint32_t a_lane_off = (uint32_t)((lane & 15) * 144 + ((lane >> 4) << 4));
    const uint32_t b_lane_off = (uint32_t)(((lane & 7) + ((lane >> 4) << 3)) * 144
                                           + (((lane >> 3) & 1) << 4));

    uint32_t af[2][4][4], bf[2][8][2];

    auto fetch_a = [&](uint32_t ab, int ks, int buf) {
#pragma unroll
        for (int mt = 0; mt < 4; mt++)
            ldm4(af[buf][mt], ab + (uint32_t)(mt * 16 * 144 + ks * 32));
    };
    auto fetch_b = [&](uint32_t bb, int ks, int buf) {
#pragma unroll
        for (int p = 0; p < 4; p++) {
            uint32_t r4[4];
            ldm4(r4, bb + (uint32_t)(p * 16 * 144 + ks * 32));
            bf[buf][2 * p][0] = r4[0]; bf[buf][2 * p][1] = r4[1];
            bf[buf][2 * p + 1][0] = r4[2]; bf[buf][2 * p + 1][1] = r4[3];
        }
    };

    int s = 0;
    CP_WAIT1();
    __syncthreads();
    fetch_a(sbase + (uint32_t)(wm * 144) + a_lane_off, 0, 0);
    fetch_b(sbase + 18432u + (uint32_t)(wn * 144) + b_lane_off, 0, 0);

    for (int kc = 0; kc < KT; kc++) {
        const uint32_t as = sbase + s * 36864u;
        const uint32_t ab = as + (uint32_t)(wm * 144) + a_lane_off;
        const uint32_t bb = as + 18432u + (uint32_t)(wn * 144) + b_lane_off;

#pragma unroll
        for (int ks = 0; ks < 4; ks++) {
            const int cur = ks & 1, nxt = cur ^ 1;
            if (ks < 3) {
                fetch_a(ab, ks + 1, nxt);
                fetch_b(bb, ks + 1, nxt);
            } else if (kc + 1 < KT) {
                CP_WAIT0();
                __syncthreads();
                const uint32_t as1 = sbase + (s ^ 1) * 36864u;
                fetch_a(as1 + (uint32_t)(wm * 144) + a_lane_off, 0, nxt);
                fetch_b(as1 + 18432u + (uint32_t)(wn * 144) + b_lane_off, 0, nxt);
                if (kc + 2 < KT) load(kc + 2, s);
            }
#pragma unroll
            for (int mt = 0; mt < 4; mt++)
#pragma unroll
                for (int nt = 0; nt < 8; nt++)
                    mma16h(acc[mt][nt], af[cur][mt], bf[cur][nt]);
        }
        s ^= 1;
    }

    // epilogue
#pragma unroll
    for (int mt = 0; mt < 4; mt++) {
#pragma unroll
        for (int half = 0; half < 2; half++) {
            const int r = m0 + wm + mt * 16 + q + half * 8;
#pragma unroll
            for (int nt = 0; nt < 8; nt++) {
                int n = n0 + wn + nt * 8 + 2 * t;
                float2 c = __half22float2(*(__half2*)&acc[mt][nt][half]);
                float vx = c.x, vy = c.y;
                if (BIAS) { float2 b = *(const float2*)&bias[n]; vx += b.x; vy += b.y; }
                if (RESM == 2) {
                    const __half2 rr = *(const __half2*)((const __half*)resv + (size_t)r * N + n);
                    vx += __half2float(rr.x); vy += __half2float(rr.y);
                }
                if (HALF_OUT)
                    *(__half2*)((__half*)Cv + (size_t)r * N + n) = __floats2half2_rn(vx, vy);
                else
                    *(float2*)((float*)Cv + (size_t)r * N + n) = make_float2(vx, vy);
            }
        }
    }
}

// ---------------- fp16 dual GEMM (fp16 acc), 2-stage, 3 CTAs/SM ------------
template <int K>
__global__ void __launch_bounds__(128, 3) gemm_dual_h(
    const __half* __restrict__ A, const __half* __restrict__ B1,
    const __half* __restrict__ B2, __half* __restrict__ C)
{
    extern __shared__ __half sh[];
    const int tid = threadIdx.x, wid = tid >> 5, lane = tid & 31;
    const int q = lane >> 2, t = lane & 3;
    const int m0 = blockIdx.y * 128, n0 = blockIdx.x * 64;
    const int wm = (wid >> 1) * 64, wn = (wid & 1) * 32;
    constexpr int KT = K >> 6;
    const uint32_t sbase = smem_u32(sh);
    const bool interior = (n0 + 64 <= HIDDEN);

    const int lr = tid >> 3, lc = tid & 7;
    const __half* Ab  = A + (size_t)(m0 + lr) * K + lc * 8;
    const int  brow   = n0 + lr;
    const uint32_t dA  = sbase + (uint32_t)(lr * 144 + lc * 16);
    const uint32_t dB1 = dA + 18432u;
    const uint32_t dB2 = dA + 27648u;

    auto load = [&](int kc_, int s) {
        const int k0 = kc_ << 6;
        const uint32_t so = (uint32_t)(s * 36864);
#pragma unroll
        for (int i = 0; i < 8; i++)
            cp16(dA + so + (uint32_t)(i * 16 * 144), Ab + k0 + (size_t)i * 16 * K, 16u);
        if (interior) {
#pragma unroll
            for (int i = 0; i < 4; i++) {
                size_t off = (size_t)(brow + i * 16) * K + lc * 8 + k0;
                cp16(dB1 + so + (uint32_t)(i * 16 * 144), B1 + off, 16u);
                cp16(dB2 + so + (uint32_t)(i * 16 * 144), B2 + off, 16u);
            }
        } else {
#pragma unroll
            for (int i = 0; i < 4; i++) {
                uint32_t ok = (brow + i * 16 < HIDDEN) ? 16u : 0u;
                size_t off = (size_t)(ok ? (brow + i * 16) : 0) * K + lc * 8 + k0;
                cp16(dB1 + so + (uint32_t)(i * 16 * 144), B1 + off, ok);
                cp16(dB2 + so + (uint32_t)(i * 16 * 144), B2 + off, ok);
            }
        }
        CP_COMMIT();
    };

    uint32_t acc1[4][4][2] = {};
    uint32_t acc2[4][4][2] = {};
    load(0, 0);
    load(1, 1);

    const uint32_t a_lane_off = (uint32_t)((lane & 15) * 144 + ((lane >> 4) << 4));
    const uint32_t b_lane_off = (uint32_t)(((lane & 7) + ((lane >> 4) << 3)) * 144
                                           + (((lane >> 3) & 1) << 4));

    uint32_t af[2][4][4], b1f[2][4][2], b2f[2][4][2];

    auto fetch_a = [&](uint32_t ab, int ks, int buf) {
#pragma unroll
        for (int mt = 0; mt < 4; mt++)
            ldm4(af[buf][mt], ab + (uint32_t)(mt * 16 * 144 + ks * 32));
    };
    auto fetch_b = [&](uint32_t b1b, uint32_t b2b, int ks, int buf) {
#pragma unroll
        for (int p = 0; p < 2; p++) {
            uint32_t r4[4];
            ldm4(r4, b1b + (uint32_t)(p * 16 * 144 + ks * 32));
            b1f[buf][2 * p][0] = r4[0]; b1f[buf][2 * p][1] = r4[1];
            b1f[buf][2 * p + 1][0] = r4[2]; b1f[buf][2 * p + 1][1] = r4[3];
            ldm4(r4, b2b + (uint32_t)(p * 16 * 144 + ks * 32));
            b2f[buf][2 * p][0] = r4[0]; b2f[buf][2 * p][1] = r4[1];
            b2f[buf][2 * p + 1][0] = r4[2]; b2f[buf][2 * p + 1][1] = r4[3];
        }
    };

    int s = 0;
    CP_WAIT1();
    __syncthreads();
    fetch_a(sbase + (uint32_t)(wm * 144) + a_lane_off, 0, 0);
    fetch_b(sbase + 18432u + (uint32_t)(wn * 144) + b_lane_off,
            sbase + 27648u + (uint32_t)(wn * 144) + b_lane_off, 0, 0);

    for (int kc = 0; kc < KT; kc++) {
        const uint32_t as  = sbase + s * 36864u;
        const uint32_t ab  = as + (uint32_t)(wm * 144) + a_lane_off;
        const uint32_t b1b = as + 18432u + (uint32_t)(wn * 144) + b_lane_off;
        const uint32_t b2b = as + 27648u + (uint32_t)(wn * 144) + b_lane_off;

#pragma unroll
        for (int ks = 0; ks < 4; ks++) {
            const int cur = ks & 1, nxt = cur ^ 1;
            if (ks < 3) {
                fetch_a(ab, ks + 1, nxt);
                fetch_b(b1b, b2b, ks + 1, nxt);
            } else if (kc + 1 < KT) {
                CP_WAIT0();
                __syncthreads();
                const uint32_t as1 = sbase + (s ^ 1) * 36864u;
                fetch_a(as1 + (uint32_t)(wm * 144) + a_lane_off, 0, nxt);
                fetch_b(as1 + 18432u + (uint32_t)(wn * 144) + b_lane_off,
                        as1 + 27648u + (uint32_t)(wn * 144) + b_lane_off, 0, nxt);
                if (kc + 2 < KT) load(kc + 2, s);
            }
#pragma unroll
            for (int mt = 0; mt < 4; mt++)
#pragma unroll
                for (int nt = 0; nt < 4; nt++) {
                    mma16h(acc1[mt][nt], af[cur][mt], b1f[cur][nt]);
                    mma16h(acc2[mt][nt], af[cur][mt], b2f[cur][nt]);
                }
        }
        s ^= 1;
    }

    // epilogue: silu(acc1) * acc2 -> fp16 (pads come out zero)
#pragma unroll
    for (int mt = 0; mt < 4; mt++) {
#pragma unroll
        for (int half = 0; half < 2; half++) {
            const int r = m0 + wm + mt * 16 + q + half * 8;
            __half* Crow = C + (size_t)r * HPAD;
#pragma unroll
            for (int nt = 0; nt < 4; nt++) {
                int n = n0 + wn + nt * 8 + 2 * t;
                float2 u = __half22float2(*(__half2*)&acc1[mt][nt][half]);
                float2 v = __half22float2(*(__half2*)&acc2[mt][nt][half]);
                float o0 = u.x / (1.f + __expf(-u.x)) * v.x;
                float o1 = u.y / (1.f + __expf(-u.y)) * v.y;
                *(__half2*)&Crow[n] = __floats2half2_rn(o0, o1);
            }
        }
    }
}

// ---------------- launch ---------------------------------------------------
extern "C" void kernel_launch(void* const* d_in, const int* in_sizes, int n_in,
                              void* d_out, int out_size)
{
    const float* x          = (const float*)d_in[0];
    const float* state      = (const float*)d_in[1];
    const float* g1         = (const float*)d_in[2];
    const float* g2         = (const float*)d_in[3];
    const float* in_proj_w  = (const float*)d_in[4];
    const float* in_proj_b  = (const float*)d_in[5];
    const float* out_proj_w = (const float*)d_in[6];
    const float* out_proj_b = (const float*)d_in[7];
    const float* w1         = (const float*)d_in[8];
    const float* w2         = (const float*)d_in[9];
    const float* w3         = (const float*)d_in[10];
    float* out = (float*)d_out;

    const float* wv = in_proj_w + (size_t)2 * DIM * DIM;
    const float* bv = in_proj_b + 2 * DIM;

    __half *h1h, *h2h, *hn1, *vh, *hn2, *ffh, *wvh, *owh, *w1h, *w2h, *w3h;
    cudaGetSymbolAddress((void**)&h1h, g_h1h);
    cudaGetSymbolAddress((void**)&h2h, g_h2h);
    cudaGetSymbolAddress((void**)&hn1, g_hn1);
    cudaGetSymbolAddress((void**)&vh,  g_vh);
    cudaGetSymbolAddress((void**)&hn2, g_hn2);
    cudaGetSymbolAddress((void**)&ffh, g_ffh);
    cudaGetSymbolAddress((void**)&wvh, g_wvh);
    cudaGetSymbolAddress((void**)&owh, g_owh);
    cudaGetSymbolAddress((void**)&w1h, g_w1h);
    cudaGetSymbolAddress((void**)&w2h, g_w2h);
    cudaGetSymbolAddress((void**)&w3h, g_w3h);

    const int SMEM = 73728;   // 2 stages x 36864 B -> 3 CTAs/SM
    cudaFuncSetAttribute((const void*)gemm_h<true,  0, true,  DIM, DIM >, cudaFuncAttributeMaxDynamicSharedMemorySize, SMEM);
    cudaFuncSetAttribute((const void*)gemm_h<true,  2, true,  DIM, DIM >, cudaFuncAttributeMaxDynamicSharedMemorySize, SMEM);
    cudaFuncSetAttribute((const void*)gemm_h<false, 2, false, DIM, HPAD>, cudaFuncAttributeMaxDynamicSharedMemorySize, SMEM);
    cudaFuncSetAttribute((const void*)gemm_dual_h<DIM>,                   cudaFuncAttributeMaxDynamicSharedMemorySize, SMEM);

    // 0. weight conversions (single merged kernel, incl. w3 pad)
    f2h_all_kernel<<<(TOT_F4 + 255) / 256, 256>>>(wv, out_proj_w, w1, w2, w3,
                                                  wvh, owh, w1h, w2h, w3h);

    // 1. h1 = x + state -> fp16 ; hn1 = rmsnorm(h1, g1) -> fp16
    rmsnorm_add_kernel<<<BATCH, 256>>>(x, state, g1, h1h, hn1);

    // 2. v = hn1 @ wv^T + bv -> fp16
    gemm_h<true, 0, true, DIM, DIM><<<dim3(DIM / 128, BATCH / 128), 128, SMEM>>>(
        hn1, wvh, bv, nullptr, vh);

    // 3. h2 = h1 + v @ out_proj_w^T + out_proj_b -> fp16 (fp16 residual)
    gemm_h<true, 2, true, DIM, DIM><<<dim3(DIM / 128, BATCH / 128), 128, SMEM>>>(
        vh, owh, out_proj_b, h1h, h2h);

    // 4. hn2 = rmsnorm(h2, g2) -> fp16
    rmsnorm_h_kernel<<<BATCH, 256>>>(h2h, g2, hn2);

    // 5. ffh = silu(hn2 @ w1^T) * (hn2 @ w2^T) -> fp16 (padded to HPAD)
    gemm_dual_h<DIM><<<dim3(HPAD / 64, BATCH / 128), 128, SMEM>>>(
        hn2, w1h, w2h, ffh);

    // 6. out = h2 + ffh @ w3^T -> fp32 (K = HPAD; fp16 residual)
    gemm_h<false, 2, false, DIM, HPAD><<<dim3(DIM / 128, BATCH / 128), 128, SMEM>>>(
        ffh, w3h, nullptr, h2h, out);
}

// round 17
// speedup vs baseline: 1.0942x; 1.0016x over previous
#include <cuda_runtime.h>
#include <cuda_fp16.h>
#include <cstdint>
#include <math.h>

#define DIM     2048
#define HIDDEN  5324
#define HPAD    5376
#define BATCH   16384

// ---------------- scratch ---------------------------------------------------
__device__ __half g_h1h[BATCH * DIM];               // fp16 residual 1
__device__ __half g_h2h[BATCH * DIM];               // fp16 residual 2
__device__ __half g_hn1[BATCH * DIM];
__device__ __half g_vh [BATCH * DIM];
__device__ __half g_hn2[BATCH * DIM];
__device__ __half g_ffh[(size_t)BATCH * HPAD];
__device__ __half g_wvh [DIM * DIM];
__device__ __half g_owh [DIM * DIM];
__device__ __half g_w1h [(size_t)HIDDEN * DIM];
__device__ __half g_w2h [(size_t)HIDDEN * DIM];
__device__ __half g_w3h [(size_t)DIM * HPAD];

// ---------------- PTX helpers ----------------------------------------------
__device__ __forceinline__ uint32_t smem_u32(const void* p) {
    uint32_t a;
    asm("{ .reg .u64 t; cvta.to.shared.u64 t, %1; cvt.u32.u64 %0, t; }"
        : "=r"(a) : "l"(p));
    return a;
}
__device__ __forceinline__ void cp16(uint32_t dst, const void* src, uint32_t sz) {
    asm volatile("cp.async.cg.shared.global [%0], [%1], 16, %2;"
                 :: "r"(dst), "l"(src), "r"(sz));
}
#define CP_COMMIT()  asm volatile("cp.async.commit_group;" ::: "memory")
#define CP_WAIT0()   asm volatile("cp.async.wait_group 0;" ::: "memory")
#define CP_WAIT1()   asm volatile("cp.async.wait_group 1;" ::: "memory")

__device__ __forceinline__ void ldm4(uint32_t* r, uint32_t addr) {
    asm volatile("ldmatrix.sync.aligned.m8n8.x4.shared.b16 {%0,%1,%2,%3}, [%4];"
                 : "=r"(r[0]), "=r"(r[1]), "=r"(r[2]), "=r"(r[3]) : "r"(addr));
}
// m16n8k16 fp16 HMMA, fp16 accumulate
__device__ __forceinline__ void mma16h(uint32_t* c, const uint32_t* a, const uint32_t* b) {
    asm volatile(
        "mma.sync.aligned.m16n8k16.row.col.f16.f16.f16.f16 "
        "{%0,%1}, {%2,%3,%4,%5}, {%6,%7}, {%0,%1};"
        : "+r"(c[0]), "+r"(c[1])
        : "r"(a[0]), "r"(a[1]), "r"(a[2]), "r"(a[3]), "r"(b[0]), "r"(b[1]));
}

// ---------------- merged prologue: rmsnorm_add + all weight conversions -----
// Blocks [0, BATCH): h1 = x+state -> fp16; hn1 = rmsnorm(h1,g1) -> fp16.
// Blocks [BATCH, BATCH+CONV_BLOCKS): fp32->fp16 convert wv/ow/w1/w2 + w3 pad.
#define N1_F4 (DIM * DIM / 4)
#define N2_F4 (HIDDEN * DIM / 4)
#define N3_F4 (DIM * HPAD / 4)
#define TOT_F4 (2 * N1_F4 + 2 * N2_F4 + N3_F4)
#define CONV_BLOCKS ((TOT_F4 + 255) / 256)

__global__ void __launch_bounds__(256) prologue_kernel(
    const float* __restrict__ x, const float* __restrict__ state,
    const float* __restrict__ g1,
    __half* __restrict__ h_out, __half* __restrict__ hn_out,
    const float* __restrict__ wv, const float* __restrict__ ow,
    const float* __restrict__ w1, const float* __restrict__ w2,
    const float* __restrict__ w3,
    __half* __restrict__ wvh, __half* __restrict__ owh,
    __half* __restrict__ w1h, __half* __restrict__ w2h,
    __half* __restrict__ w3h)
{
    if (blockIdx.x < BATCH) {
        // ---- rmsnorm_add path ----
        const int row = blockIdx.x;
        const size_t base = (size_t)row * DIM;
        const float4* a4 = (const float4*)(x + base);
        const float4* b4 = (const float4*)(state + base);
        const float4* g4 = (const float4*)g1;

        float4 v[2];
        float ss = 0.f;
#pragma unroll
        for (int i = 0; i < 2; i++) {
            int idx = threadIdx.x + i * 256;
            float4 xx = a4[idx];
            float4 yy = b4[idx];
            xx.x += yy.x; xx.y += yy.y; xx.z += yy.z; xx.w += yy.w;
            v[i] = xx;
            ss += xx.x * xx.x + xx.y * xx.y + xx.z * xx.z + xx.w * xx.w;
        }
        __shared__ float red[8];
#pragma unroll
        for (int o = 16; o; o >>= 1) ss += __shfl_xor_sync(0xffffffffu, ss, o);
        if ((threadIdx.x & 31) == 0) red[threadIdx.x >> 5] = ss;
        __syncthreads();
        float tot = red[0] + red[1] + red[2] + red[3] + red[4] + red[5] + red[6] + red[7];

        const float inv = 0.022097086912079613f / fmaxf(sqrtf(tot), 1e-12f);

        __half2* h2p  = (__half2*)(h_out + base);
        __half2* hn2p = (__half2*)(hn_out + base);
#pragma unroll
        for (int i = 0; i < 2; i++) {
            int idx = threadIdx.x + i * 256;
            float4 xx = v[i];
            h2p[idx * 2 + 0] = __floats2half2_rn(xx.x, xx.y);
            h2p[idx * 2 + 1] = __floats2half2_rn(xx.z, xx.w);
            float4 gg = g4[idx];
            hn2p[idx * 2 + 0] = __floats2half2_rn(xx.x * inv * gg.x, xx.y * inv * gg.y);
            hn2p[idx * 2 + 1] = __floats2half2_rn(xx.z * inv * gg.z, xx.w * inv * gg.w);
        }
    } else {
        // ---- weight conversion path ----
        int i = (blockIdx.x - BATCH) * 256 + threadIdx.x;
        if (i >= TOT_F4) return;
        if (i < 2 * N1_F4 + 2 * N2_F4) {
            const float* s;  __half* d;  int j;
            if      (i < N1_F4)             { s = wv; d = wvh; j = i; }
            else if (i < 2 * N1_F4)         { s = ow; d = owh; j = i - N1_F4; }
            else if (i < 2 * N1_F4 + N2_F4) { s = w1; d = w1h; j = i - 2 * N1_F4; }
            else                            { s = w2; d = w2h; j = i - 2 * N1_F4 - N2_F4; }
            float4 v = ((const float4*)s)[j];
            __half2* o = (__half2*)d + j * 2;
            o[0] = __floats2half2_rn(v.x, v.y);
            o[1] = __floats2half2_rn(v.z, v.w);
        } else {
            int j = i - (2 * N1_F4 + 2 * N2_F4);
            int r = j / (HPAD / 4), cg = j - r * (HPAD / 4);
            int c = cg * 4;
            float4 v = make_float4(0.f, 0.f, 0.f, 0.f);
            if (c < HIDDEN)
                v = *(const float4*)&w3[(size_t)r * HIDDEN + c];
            __half2* o = (__half2*)(w3h + (size_t)r * HPAD + c);
            o[0] = __floats2half2_rn(v.x, v.y);
            o[1] = __floats2half2_rn(v.z, v.w);
        }
    }
}

// ---------------- rmsnorm (fp16 in) -> fp16 out -----------------------------
__global__ void __launch_bounds__(256) rmsnorm_h_kernel(
    const __half* __restrict__ a, const float* __restrict__ g,
    __half* __restrict__ hn)
{
    const int row = blockIdx.x;
    const size_t base = (size_t)row * DIM;
    uint4 pk = ((const uint4*)(a + base))[threadIdx.x];
    __half2* hp = (__half2*)&pk;
    float2 f[4];
    float ss = 0.f;
#pragma unroll
    for (int k = 0; k < 4; k++) {
        f[k] = __half22float2(hp[k]);
        ss += f[k].x * f[k].x + f[k].y * f[k].y;
    }
    __shared__ float red[8];
#pragma unroll
    for (int o = 16; o; o >>= 1) ss += __shfl_xor_sync(0xffffffffu, ss, o);
    if ((threadIdx.x & 31) == 0) red[threadIdx.x >> 5] = ss;
    __syncthreads();
    float tot = red[0] + red[1] + red[2] + red[3] + red[4] + red[5] + red[6] + red[7];

    const float inv = 0.022097086912079613f / fmaxf(sqrtf(tot), 1e-12f);

    const float4* g4 = (const float4*)g + threadIdx.x * 2;
    float4 g0 = g4[0], g1v = g4[1];
    uint4 out;
    __half2* op = (__half2*)&out;
    op[0] = __floats2half2_rn(f[0].x * inv * g0.x, f[0].y * inv * g0.y);
    op[1] = __floats2half2_rn(f[1].x * inv * g0.z, f[1].y * inv * g0.w);
    op[2] = __floats2half2_rn(f[2].x * inv * g1v.x, f[2].y * inv * g1v.y);
    op[3] = __floats2half2_rn(f[3].x * inv * g1v.z, f[3].y * inv * g1v.w);
    ((uint4*)(hn + base))[threadIdx.x] = out;
}

// ---------------- fp16 HMMA GEMM, 2-stage, 3 CTAs/SM (R15 pipeline) ---------
// RESM: 0 none, 2 fp16 residual.
template <bool BIAS, int RESM, bool HALF_OUT, int N, int K>
__global__ void __launch_bounds__(128, 3) gemm_h(
    const __half* __restrict__ A, const __half* __restrict__ B,
    const float* __restrict__ bias, const void* __restrict__ resv,
    void* __restrict__ Cv)
{
    extern __shared__ __half sh[];
    const int tid = threadIdx.x, wid = tid >> 5, lane = tid & 31;
    const int q = lane >> 2, t = lane & 3;
    const int m0 = blockIdx.y * 128, n0 = blockIdx.x * 128;
    const int wm = (wid >> 1) * 64, wn = (wid & 1) * 64;
    constexpr int KT = K >> 6;
    const uint32_t sbase = smem_u32(sh);

    const int lr = tid >> 3, lc = tid & 7;
    const __half* Ab = A + (size_t)(m0 + lr) * K + lc * 8;
    const __half* Bb = B + (size_t)(n0 + lr) * K + lc * 8;
    const uint32_t dA = sbase + (uint32_t)(lr * 144 + lc * 16);
    const uint32_t dB = dA + 18432u;

    auto load = [&](int kc_, int s) {
        const int k0 = kc_ << 6;
        const uint32_t so = (uint32_t)(s * 36864);
#pragma unroll
        for (int i = 0; i < 8; i++)
            cp16(dA + so + (uint32_t)(i * 16 * 144), Ab + k0 + (size_t)i * 16 * K, 16u);
#pragma unroll
        for (int i = 0; i < 8; i++)
            cp16(dB + so + (uint32_t)(i * 16 * 144), Bb + k0 + (size_t)i * 16 * K, 16u);
        CP_COMMIT();
    };

    uint32_t acc[4][8][2] = {};
    load(0, 0);
    load(1, 1);

    const uint32_t a_lane_off = (uint32_t)((lane & 15) * 144 + ((lane >> 4) << 4));
    const uint32_t b_lane_off = (uint32_t)(((lane & 7) + ((lane >> 4) << 3)) * 144
                                           + (((lane >> 3) & 1) << 4));

    uint32_t af[2][4][4], bf[2][8][2];

    auto fetch_a = [&](uint32_t ab, int ks, int buf) {
#pragma unroll
        for (int mt = 0; mt < 4; mt++)
            ldm4(af[buf][mt], ab + (uint32_t)(mt * 16 * 144 + ks * 32));
    };
    auto fetch_b = [&](uint32_t bb, int ks, int buf) {
#pragma unroll
        for (int p = 0; p < 4; p++) {
            uint32_t r4[4];
            ldm4(r4, bb + (uint32_t)(p * 16 * 144 + ks * 32));
            bf[buf][2 * p][0] = r4[0]; bf[buf][2 * p][1] = r4[1];
            bf[buf][2 * p + 1][0] = r4[2]; bf[buf][2 * p + 1][1] = r4[3];
        }
    };

    int s = 0;
    CP_WAIT1();
    __syncthreads();
    fetch_a(sbase + (uint32_t)(wm * 144) + a_lane_off, 0, 0);
    fetch_b(sbase + 18432u + (uint32_t)(wn * 144) + b_lane_off, 0, 0);

    for (int kc = 0; kc < KT; kc++) {
        const uint32_t as = sbase + s * 36864u;
        const uint32_t ab = as + (uint32_t)(wm * 144) + a_lane_off;
        const uint32_t bb = as + 18432u + (uint32_t)(wn * 144) + b_lane_off;

#pragma unroll
        for (int ks = 0; ks < 4; ks++) {
            const int cur = ks & 1, nxt = cur ^ 1;
            if (ks < 3) {
                fetch_a(ab, ks + 1, nxt);
                fetch_b(bb, ks + 1, nxt);
            } else if (kc + 1 < KT) {
                CP_WAIT0();
                __syncthreads();
                const uint32_t as1 = sbase + (s ^ 1) * 36864u;
                fetch_a(as1 + (uint32_t)(wm * 144) + a_lane_off, 0, nxt);
                fetch_b(as1 + 18432u + (uint32_t)(wn * 144) + b_lane_off, 0, nxt);
                if (kc + 2 < KT) load(kc + 2, s);
            }
#pragma unroll
            for (int mt = 0; mt < 4; mt++)
#pragma unroll
                for (int nt = 0; nt < 8; nt++)
                    mma16h(acc[mt][nt], af[cur][mt], bf[cur][nt]);
        }
        s ^= 1;
    }

    // epilogue
#pragma unroll
    for (int mt = 0; mt < 4; mt++) {
#pragma unroll
        for (int half = 0; half < 2; half++) {
            const int r = m0 + wm + mt * 16 + q + half * 8;
#pragma unroll
            for (int nt = 0; nt < 8; nt++) {
                int n = n0 + wn + nt * 8 + 2 * t;
                float2 c = __half22float2(*(__half2*)&acc[mt][nt][half]);
                float vx = c.x, vy = c.y;
                if (BIAS) { float2 b = *(const float2*)&bias[n]; vx += b.x; vy += b.y; }
                if (RESM == 2) {
                    const __half2 rr = *(const __half2*)((const __half*)resv + (size_t)r * N + n);
                    vx += __half2float(rr.x); vy += __half2float(rr.y);
                }
                if (HALF_OUT)
                    *(__half2*)((__half*)Cv + (size_t)r * N + n) = __floats2half2_rn(vx, vy);
                else
                    *(float2*)((float*)Cv + (size_t)r * N + n) = make_float2(vx, vy);
            }
        }
    }
}

// ---------------- fp16 dual GEMM (fp16 acc), 2-stage, 3 CTAs/SM ------------
template <int K>
__global__ void __launch_bounds__(128, 3) gemm_dual_h(
    const __half* __restrict__ A, const __half* __restrict__ B1,
    const __half* __restrict__ B2, __half* __restrict__ C)
{
    extern __shared__ __half sh[];
    const int tid = threadIdx.x, wid = tid >> 5, lane = tid & 31;
    const int q = lane >> 2, t = lane & 3;
    const int m0 = blockIdx.y * 128, n0 = blockIdx.x * 64;
    const int wm = (wid >> 1) * 64, wn = (wid & 1) * 32;
    constexpr int KT = K >> 6;
    const uint32_t sbase = smem_u32(sh);
    const bool interior = (n0 + 64 <= HIDDEN);

    const int lr = tid >> 3, lc = tid & 7;
    const __half* Ab  = A + (size_t)(m0 + lr) * K + lc * 8;
    const int  brow   = n0 + lr;
    const uint32_t dA  = sbase + (uint32_t)(lr * 144 + lc * 16);
    const uint32_t dB1 = dA + 18432u;
    const uint32_t dB2 = dA + 27648u;

    auto load = [&](int kc_, int s) {
        const int k0 = kc_ << 6;
        const uint32_t so = (uint32_t)(s * 36864);
#pragma unroll
        for (int i = 0; i < 8; i++)
            cp16(dA + so + (uint32_t)(i * 16 * 144), Ab + k0 + (size_t)i * 16 * K, 16u);
        if (interior) {
#pragma unroll
            for (int i = 0; i < 4; i++) {
                size_t off = (size_t)(brow + i * 16) * K + lc * 8 + k0;
                cp16(dB1 + so + (uint32_t)(i * 16 * 144), B1 + off, 16u);
                cp16(dB2 + so + (uint32_t)(i * 16 * 144), B2 + off, 16u);
            }
        } else {
#pragma unroll
            for (int i = 0; i < 4; i++) {
                uint32_t ok = (brow + i * 16 < HIDDEN) ? 16u : 0u;
                size_t off = (size_t)(ok ? (brow + i * 16) : 0) * K + lc * 8 + k0;
                cp16(dB1 + so + (uint32_t)(i * 16 * 144), B1 + off, ok);
                cp16(dB2 + so + (uint32_t)(i * 16 * 144), B2 + off, ok);
            }
        }
        CP_COMMIT();
    };

    uint32_t acc1[4][4][2] = {};
    uint32_t acc2[4][4][2] = {};
    load(0, 0);
    load(1, 1);

    const uint32_t a_lane_off = (uint32_t)((lane & 15) * 144 + ((lane >> 4) << 4));
    const uint32_t b_lane_off = (uint32_t)(((lane & 7) + ((lane >> 4) << 3)) * 144
                                           + (((lane >> 3) & 1) << 4));

    uint32_t af[2][4][4], b1f[2][4][2], b2f[2][4][2];

    auto fetch_a = [&](uint32_t ab, int ks, int buf) {
#pragma unroll
        for (int mt = 0; mt < 4; mt++)
            ldm4(af[buf][mt], ab + (uint32_t)(mt * 16 * 144 + ks * 32));
    };
    auto fetch_b = [&](uint32_t b1b, uint32_t b2b, int ks, int buf) {
#pragma unroll
        for (int p = 0; p < 2; p++) {
            uint32_t r4[4];
            ldm4(r4, b1b + (uint32_t)(p * 16 * 144 + ks * 32));
            b1f[buf][2 * p][0] = r4[0]; b1f[buf][2 * p][1] = r4[1];
            b1f[buf][2 * p + 1][0] = r4[2]; b1f[buf][2 * p + 1][1] = r4[3];
            ldm4(r4, b2b + (uint32_t)(p * 16 * 144 + ks * 32));
            b2f[buf][2 * p][0] = r4[0]; b2f[buf][2 * p][1] = r4[1];
            b2f[buf][2 * p + 1][0] = r4[2]; b2f[buf][2 * p + 1][1] = r4[3];
        }
    };

    int s = 0;
    CP_WAIT1();
    __syncthreads();
    fetch_a(sbase + (uint32_t)(wm * 144) + a_lane_off, 0, 0);
    fetch_b(sbase + 18432u + (uint32_t)(wn * 144) + b_lane_off,
            sbase + 27648u + (uint32_t)(wn * 144) + b_lane_off, 0, 0);

    for (int kc = 0; kc < KT; kc++) {
        const uint32_t as  = sbase + s * 36864u;
        const uint32_t ab  = as + (uint32_t)(wm * 144) + a_lane_off;
        const uint32_t b1b = as + 18432u + (uint32_t)(wn * 144) + b_lane_off;
        const uint32_t b2b = as + 27648u + (uint32_t)(wn * 144) + b_lane_off;

#pragma unroll
        for (int ks = 0; ks < 4; ks++) {
            const int cur = ks & 1, nxt = cur ^ 1;
            if (ks < 3) {
                fetch_a(ab, ks + 1, nxt);
                fetch_b(b1b, b2b, ks + 1, nxt);
            } else if (kc + 1 < KT) {
                CP_WAIT0();
                __syncthreads();
                const uint32_t as1 = sbase + (s ^ 1) * 36864u;
                fetch_a(as1 + (uint32_t)(wm * 144) + a_lane_off, 0, nxt);
                fetch_b(as1 + 18432u + (uint32_t)(wn * 144) + b_lane_off,
                        as1 + 27648u + (uint32_t)(wn * 144) + b_lane_off, 0, nxt);
                if (kc + 2 < KT) load(kc + 2, s);
            }
#pragma unroll
            for (int mt = 0; mt < 4; mt++)
#pragma unroll
                for (int nt = 0; nt < 4; nt++) {
                    mma16h(acc1[mt][nt], af[cur][mt], b1f[cur][nt]);
                    mma16h(acc2[mt][nt], af[cur][mt], b2f[cur][nt]);
                }
        }
        s ^= 1;
    }

    // epilogue: silu(acc1) * acc2 -> fp16 (pads come out zero)
#pragma unroll
    for (int mt = 0; mt < 4; mt++) {
#pragma unroll
        for (int half = 0; half < 2; half++) {
            const int r = m0 + wm + mt * 16 + q + half * 8;
            __half* Crow = C + (size_t)r * HPAD;
#pragma unroll
            for (int nt = 0; nt < 4; nt++) {
                int n = n0 + wn + nt * 8 + 2 * t;
                float2 u = __half22float2(*(__half2*)&acc1[mt][nt][half]);
                float2 v = __half22float2(*(__half2*)&acc2[mt][nt][half]);
                float o0 = u.x / (1.f + __expf(-u.x)) * v.x;
                float o1 = u.y / (1.f + __expf(-u.y)) * v.y;
                *(__half2*)&Crow[n] = __floats2half2_rn(o0, o1);
            }
        }
    }
}

// ---------------- launch ---------------------------------------------------
extern "C" void kernel_launch(void* const* d_in, const int* in_sizes, int n_in,
                              void* d_out, int out_size)
{
    const float* x          = (const float*)d_in[0];
    const float* state      = (const float*)d_in[1];
    const float* g1         = (const float*)d_in[2];
    const float* g2         = (const float*)d_in[3];
    const float* in_proj_w  = (const float*)d_in[4];
    const float* in_proj_b  = (const float*)d_in[5];
    const float* out_proj_w = (const float*)d_in[6];
    const float* out_proj_b = (const float*)d_in[7];
    const float* w1         = (const float*)d_in[8];
    const float* w2         = (const float*)d_in[9];
    const float* w3         = (const float*)d_in[10];
    float* out = (float*)d_out;

    const float* wv = in_proj_w + (size_t)2 * DIM * DIM;
    const float* bv = in_proj_b + 2 * DIM;

    __half *h1h, *h2h, *hn1, *vh, *hn2, *ffh, *wvh, *owh, *w1h, *w2h, *w3h;
    cudaGetSymbolAddress((void**)&h1h, g_h1h);
    cudaGetSymbolAddress((void**)&h2h, g_h2h);
    cudaGetSymbolAddress((void**)&hn1, g_hn1);
    cudaGetSymbolAddress((void**)&vh,  g_vh);
    cudaGetSymbolAddress((void**)&hn2, g_hn2);
    cudaGetSymbolAddress((void**)&ffh, g_ffh);
    cudaGetSymbolAddress((void**)&wvh, g_wvh);
    cudaGetSymbolAddress((void**)&owh, g_owh);
    cudaGetSymbolAddress((void**)&w1h, g_w1h);
    cudaGetSymbolAddress((void**)&w2h, g_w2h);
    cudaGetSymbolAddress((void**)&w3h, g_w3h);

    const int SMEM = 73728;   // 2 stages x 36864 B -> 3 CTAs/SM
    cudaFuncSetAttribute((const void*)gemm_h<true,  0, true,  DIM, DIM >, cudaFuncAttributeMaxDynamicSharedMemorySize, SMEM);
    cudaFuncSetAttribute((const void*)gemm_h<true,  2, true,  DIM, DIM >, cudaFuncAttributeMaxDynamicSharedMemorySize, SMEM);
    cudaFuncSetAttribute((const void*)gemm_h<false, 2, false, DIM, HPAD>, cudaFuncAttributeMaxDynamicSharedMemorySize, SMEM);
    cudaFuncSetAttribute((const void*)gemm_dual_h<DIM>,                   cudaFuncAttributeMaxDynamicSharedMemorySize, SMEM);

    // 0+1. merged prologue: weight conversions || (h1 = x+state; hn1 = rmsnorm)
    prologue_kernel<<<BATCH + CONV_BLOCKS, 256>>>(
        x, state, g1, h1h, hn1,
        wv, out_proj_w, w1, w2, w3, wvh, owh, w1h, w2h, w3h);

    // 2. v = hn1 @ wv^T + bv -> fp16
    gemm_h<true, 0, true, DIM, DIM><<<dim3(DIM / 128, BATCH / 128), 128, SMEM>>>(
        hn1, wvh, bv, nullptr, vh);

    // 3. h2 = h1 + v @ out_proj_w^T + out_proj_b -> fp16 (fp16 residual)
    gemm_h<true, 2, true, DIM, DIM><<<dim3(DIM / 128, BATCH / 128), 128, SMEM>>>(
        vh, owh, out_proj_b, h1h, h2h);

    // 4. hn2 = rmsnorm(h2, g2) -> fp16
    rmsnorm_h_kernel<<<BATCH, 256>>>(h2h, g2, hn2);

    // 5. ffh = silu(hn2 @ w1^T) * (hn2 @ w2^T) -> fp16 (padded to HPAD)
    gemm_dual_h<DIM><<<dim3(HPAD / 64, BATCH / 128), 128, SMEM>>>(
        hn2, w1h, w2h, ffh);

    // 6. out = h2 + ffh @ w3^T -> fp32 (K = HPAD; fp16 residual)
    gemm_h<false, 2, false, DIM, HPAD><<<dim3(DIM / 128, BATCH / 128), 128, SMEM>>>(
        ffh, w3h, nullptr, h2h, out);
}